// round 4
// baseline (speedup 1.0000x reference)
#include <cuda_runtime.h>
#include <math.h>

#define HID 256
#define NLAYERS 15
#define MAXN 50000
#define MAXE 500000
#define EPS 1e-5f

// ---------------- scratch (static device globals) --------------------------
__device__ float g_h[(size_t)MAXN * HID];
__device__ float g_agg[(size_t)MAXN * HID];
__device__ float g_out[(size_t)MAXN * HID];
__device__ float g_z1[(size_t)MAXE * HID];
__device__ float g_z2[(size_t)MAXE * HID];
__device__ float g_sum[HID];
__device__ float g_sq[HID];
__device__ float g_scale[HID];
__device__ float g_shift[HID];
// CSR scratch
__device__ int g_cnt[MAXN];
__device__ int g_rowptr[MAXN + 1];
__device__ int g_cur[MAXN];
__device__ int g_csr[MAXE];

// ---------------- input fc: h = x @ W_in^T (IN_CH=2) -----------------------
__global__ void k_input(const float* __restrict__ x,
                        const float* __restrict__ Win, int N) {
    int i = blockIdx.x;
    int j = threadIdx.x;
    if (i < N)
        g_h[(size_t)i * HID + j] =
            fmaf(x[2 * i], Win[2 * j], x[2 * i + 1] * Win[2 * j + 1]);
}

// ---------------- CSR build (runs once per call, trivial cost) -------------
__global__ void k_zero_cnt(int N) {
    int i = blockIdx.x * blockDim.x + threadIdx.x;
    if (i < N) g_cnt[i] = 0;
}
__global__ void k_hist(const int* __restrict__ ei, int E) {
    int e = blockIdx.x * blockDim.x + threadIdx.x;
    if (e < E) atomicAdd(&g_cnt[ei[E + e]], 1);
}
__global__ void k_scan(int N) {
    __shared__ int s[1024];
    int t = threadIdx.x;
    int chunk = (N + 1023) / 1024;
    int lo = t * chunk, hi = min(lo + chunk, N);
    int sum = 0;
    for (int i = lo; i < hi; i++) sum += g_cnt[i];
    s[t] = sum;
    __syncthreads();
    for (int off = 1; off < 1024; off <<= 1) {
        int v = (t >= off) ? s[t - off] : 0;
        __syncthreads();
        s[t] += v;
        __syncthreads();
    }
    int run = (t == 0) ? 0 : s[t - 1];
    for (int i = lo; i < hi; i++) {
        g_rowptr[i] = run;
        g_cur[i] = run;
        run += g_cnt[i];
    }
    if (t == 0) g_rowptr[N] = s[1023];
}
__global__ void k_fill(const int* __restrict__ ei, int E) {
    int e = blockIdx.x * blockDim.x + threadIdx.x;
    if (e < E) {
        int d = ei[E + e];
        int p = atomicAdd(&g_cur[d], 1);
        g_csr[p] = ei[e];
    }
}

// ---------------- CSR aggregate: agg[i] = sum_{e: dst=i} h[src[e]] ---------
__global__ void __launch_bounds__(256) k_aggr(int N) {
    int node = blockIdx.x * 4 + (threadIdx.x >> 6);
    int lane = threadIdx.x & 63;
    if (node >= N) return;
    int s = g_rowptr[node], e = g_rowptr[node + 1];
    float4 acc = make_float4(0.f, 0.f, 0.f, 0.f);
    for (int i = s; i < e; i++) {
        int src = g_csr[i];
        float4 v = *reinterpret_cast<const float4*>(
            g_h + (size_t)src * HID + lane * 4);
        acc.x += v.x; acc.y += v.y; acc.z += v.z; acc.w += v.w;
    }
    *reinterpret_cast<float4*>(g_agg + (size_t)node * HID + lane * 4) = acc;
}

// ---------------- 128x128x8 fp32 GEMM, 8x8 per thread ----------------------
#define TBM 128
#define TBN 128
#define TBK 8

// fused node layer: out = agg @ Wrel^T + h @ Wroot^T + brel
__global__ void __launch_bounds__(256, 1)
k_layer_gemm(const float* __restrict__ Wrel, const float* __restrict__ Wroot,
             const float* __restrict__ brel, int M) {
    __shared__ float As[TBK][TBM];
    __shared__ float Ws[TBK][TBN];

    int bm = blockIdx.y * TBM, bn = blockIdx.x * TBN;
    int tid = threadIdx.x;
    int lr = tid >> 1, lk = (tid & 1) * 4;
    int tx = tid & 15, ty = tid >> 4;

    float acc[8][8] = {};

#pragma unroll 1
    for (int pass = 0; pass < 2; pass++) {
        const float* A = pass ? g_h : g_agg;
        const float* W = pass ? Wroot : Wrel;
        for (int k0 = 0; k0 < HID; k0 += TBK) {
            float4 v = make_float4(0.f, 0.f, 0.f, 0.f);
            int gr = bm + lr;
            if (gr < M)
                v = *reinterpret_cast<const float4*>(
                    A + (size_t)gr * HID + k0 + lk);
            As[lk + 0][lr] = v.x; As[lk + 1][lr] = v.y;
            As[lk + 2][lr] = v.z; As[lk + 3][lr] = v.w;
            float4 w = *reinterpret_cast<const float4*>(
                W + (size_t)(bn + lr) * HID + k0 + lk);
            Ws[lk + 0][lr] = w.x; Ws[lk + 1][lr] = w.y;
            Ws[lk + 2][lr] = w.z; Ws[lk + 3][lr] = w.w;
            __syncthreads();
#pragma unroll
            for (int kk = 0; kk < TBK; kk++) {
                float a[8], b[8];
                *reinterpret_cast<float4*>(a) =
                    *reinterpret_cast<float4*>(&As[kk][ty * 8]);
                *reinterpret_cast<float4*>(a + 4) =
                    *reinterpret_cast<float4*>(&As[kk][ty * 8 + 4]);
                *reinterpret_cast<float4*>(b) =
                    *reinterpret_cast<float4*>(&Ws[kk][tx * 8]);
                *reinterpret_cast<float4*>(b + 4) =
                    *reinterpret_cast<float4*>(&Ws[kk][tx * 8 + 4]);
#pragma unroll
                for (int i = 0; i < 8; i++)
#pragma unroll
                    for (int j = 0; j < 8; j++)
                        acc[i][j] = fmaf(a[i], b[j], acc[i][j]);
            }
            __syncthreads();
        }
    }

#pragma unroll
    for (int i = 0; i < 8; i++) {
        int r = bm + ty * 8 + i;
        if (r >= M) continue;
        float* crow = g_out + (size_t)r * HID + bn + tx * 8;
        const float* bb = brel + bn + tx * 8;
#pragma unroll
        for (int j = 0; j < 8; j += 4) {
            float4 o;
            o.x = acc[i][j + 0] + bb[j + 0];
            o.y = acc[i][j + 1] + bb[j + 1];
            o.z = acc[i][j + 2] + bb[j + 2];
            o.w = acc[i][j + 3] + bb[j + 3];
            *reinterpret_cast<float4*>(crow + j) = o;
        }
    }
}

// edge hidden-2: z2 = relu(z1 @ W2^T + b2)
__global__ void __launch_bounds__(256, 1)
k_edge_gemm2(const float* __restrict__ W, const float* __restrict__ bias,
             int M) {
    __shared__ float As[TBK][TBM];
    __shared__ float Ws[TBK][TBN];

    int bm = blockIdx.y * TBM, bn = blockIdx.x * TBN;
    int tid = threadIdx.x;
    int lr = tid >> 1, lk = (tid & 1) * 4;
    int tx = tid & 15, ty = tid >> 4;

    float acc[8][8] = {};

    for (int k0 = 0; k0 < HID; k0 += TBK) {
        float4 v = make_float4(0.f, 0.f, 0.f, 0.f);
        int gr = bm + lr;
        if (gr < M)
            v = *reinterpret_cast<const float4*>(
                g_z1 + (size_t)gr * HID + k0 + lk);
        As[lk + 0][lr] = v.x; As[lk + 1][lr] = v.y;
        As[lk + 2][lr] = v.z; As[lk + 3][lr] = v.w;
        float4 w = *reinterpret_cast<const float4*>(
            W + (size_t)(bn + lr) * HID + k0 + lk);
        Ws[lk + 0][lr] = w.x; Ws[lk + 1][lr] = w.y;
        Ws[lk + 2][lr] = w.z; Ws[lk + 3][lr] = w.w;
        __syncthreads();
#pragma unroll
        for (int kk = 0; kk < TBK; kk++) {
            float a[8], b[8];
            *reinterpret_cast<float4*>(a) =
                *reinterpret_cast<float4*>(&As[kk][ty * 8]);
            *reinterpret_cast<float4*>(a + 4) =
                *reinterpret_cast<float4*>(&As[kk][ty * 8 + 4]);
            *reinterpret_cast<float4*>(b) =
                *reinterpret_cast<float4*>(&Ws[kk][tx * 8]);
            *reinterpret_cast<float4*>(b + 4) =
                *reinterpret_cast<float4*>(&Ws[kk][tx * 8 + 4]);
#pragma unroll
            for (int i = 0; i < 8; i++)
#pragma unroll
                for (int j = 0; j < 8; j++)
                    acc[i][j] = fmaf(a[i], b[j], acc[i][j]);
        }
        __syncthreads();
    }

#pragma unroll
    for (int i = 0; i < 8; i++) {
        int r = bm + ty * 8 + i;
        if (r >= M) continue;
        float* crow = g_z2 + (size_t)r * HID + bn + tx * 8;
        const float* bb = bias + bn + tx * 8;
#pragma unroll
        for (int j = 0; j < 8; j += 4) {
            float4 o;
            o.x = fmaxf(acc[i][j + 0] + bb[j + 0], 0.f);
            o.y = fmaxf(acc[i][j + 1] + bb[j + 1], 0.f);
            o.z = fmaxf(acc[i][j + 2] + bb[j + 2], 0.f);
            o.w = fmaxf(acc[i][j + 3] + bb[j + 3], 0.f);
            *reinterpret_cast<float4*>(crow + j) = o;
        }
    }
}

// edge hidden-1 with fused gather: z1 = relu(cat(h[src],h[dst]) @ W1^T + b1)
__global__ void __launch_bounds__(256, 1)
k_edge_gemm1(const int* __restrict__ ei, int E, const float* __restrict__ W,
             const float* __restrict__ bias) {
    __shared__ float As[TBK][TBM];
    __shared__ float Ws[TBK][TBN];
    __shared__ int s_src[TBM], s_dst[TBM];

    int bm = blockIdx.y * TBM, bn = blockIdx.x * TBN;
    int tid = threadIdx.x;
    int lr = tid >> 1, lk = (tid & 1) * 4;
    int tx = tid & 15, ty = tid >> 4;

    if (tid < TBM) {
        int e = bm + tid;
        s_src[tid] = (e < E) ? ei[e] : 0;
        s_dst[tid] = (e < E) ? ei[E + e] : 0;
    }
    __syncthreads();

    float acc[8][8] = {};

    for (int k0 = 0; k0 < 2 * HID; k0 += TBK) {
        int gr = bm + lr;
        int kg = k0 + lk;
        float4 v = make_float4(0.f, 0.f, 0.f, 0.f);
        if (gr < E) {
            int node = (kg < HID) ? s_src[lr] : s_dst[lr];
            v = *reinterpret_cast<const float4*>(
                g_h + (size_t)node * HID + (kg & (HID - 1)));
        }
        As[lk + 0][lr] = v.x; As[lk + 1][lr] = v.y;
        As[lk + 2][lr] = v.z; As[lk + 3][lr] = v.w;
        float4 w = *reinterpret_cast<const float4*>(
            W + (size_t)(bn + lr) * (2 * HID) + kg);
        Ws[lk + 0][lr] = w.x; Ws[lk + 1][lr] = w.y;
        Ws[lk + 2][lr] = w.z; Ws[lk + 3][lr] = w.w;
        __syncthreads();
#pragma unroll
        for (int kk = 0; kk < TBK; kk++) {
            float a[8], b[8];
            *reinterpret_cast<float4*>(a) =
                *reinterpret_cast<float4*>(&As[kk][ty * 8]);
            *reinterpret_cast<float4*>(a + 4) =
                *reinterpret_cast<float4*>(&As[kk][ty * 8 + 4]);
            *reinterpret_cast<float4*>(b) =
                *reinterpret_cast<float4*>(&Ws[kk][tx * 8]);
            *reinterpret_cast<float4*>(b + 4) =
                *reinterpret_cast<float4*>(&Ws[kk][tx * 8 + 4]);
#pragma unroll
            for (int i = 0; i < 8; i++)
#pragma unroll
                for (int j = 0; j < 8; j++)
                    acc[i][j] = fmaf(a[i], b[j], acc[i][j]);
        }
        __syncthreads();
    }

#pragma unroll
    for (int i = 0; i < 8; i++) {
        int r = bm + ty * 8 + i;
        if (r >= E) continue;
        float* crow = g_z1 + (size_t)r * HID + bn + tx * 8;
        const float* bb = bias + bn + tx * 8;
#pragma unroll
        for (int j = 0; j < 8; j += 4) {
            float4 o;
            o.x = fmaxf(acc[i][j + 0] + bb[j + 0], 0.f);
            o.y = fmaxf(acc[i][j + 1] + bb[j + 1], 0.f);
            o.z = fmaxf(acc[i][j + 2] + bb[j + 2], 0.f);
            o.w = fmaxf(acc[i][j + 3] + bb[j + 3], 0.f);
            *reinterpret_cast<float4*>(crow + j) = o;
        }
    }
}

// ---------------- batchnorm ------------------------------------------------
__global__ void k_bn_zero() {
    int c = threadIdx.x;
    g_sum[c] = 0.f;
    g_sq[c] = 0.f;
}
__global__ void k_bn_partial(int N) {
    int c = threadIdx.x;
    int r0 = blockIdx.x * 256;
    int r1 = min(r0 + 256, N);
    float s = 0.f, q = 0.f;
    for (int r = r0; r < r1; r++) {
        float v = g_out[(size_t)r * HID + c];
        s += v;
        q = fmaf(v, v, q);
    }
    atomicAdd(&g_sum[c], s);
    atomicAdd(&g_sq[c], q);
}
__global__ void k_bn_final(const float* __restrict__ gamma,
                           const float* __restrict__ beta, float invN) {
    int c = threadIdx.x;
    float m = g_sum[c] * invN;
    float var = g_sq[c] * invN - m * m;
    float rstd = rsqrtf(var + EPS);
    float sc = rstd * gamma[c];
    g_scale[c] = sc;
    g_shift[c] = beta[c] - m * sc;
}
__global__ void k_bn_apply(int N) {
    int i = blockIdx.x, c = threadIdx.x;
    size_t idx = (size_t)i * HID + c;
    float v = fmaf(g_out[idx], g_scale[c], g_shift[c]);
    g_h[idx] += fmaxf(v, 0.f);
}

// ---------------- final: sigmoid(z2 @ W3^T + b3) ---------------------------
__global__ void k_final(const float* __restrict__ W3,
                        const float* __restrict__ b3,
                        float* __restrict__ out, int E) {
    int w = threadIdx.x >> 5, lane = threadIdx.x & 31;
    int e = blockIdx.x * 8 + w;
    if (e >= E) return;
    const float* z = g_z2 + (size_t)e * HID;
    float s = 0.f;
#pragma unroll
    for (int i = 0; i < 8; i++)
        s = fmaf(z[lane + 32 * i], W3[lane + 32 * i], s);
#pragma unroll
    for (int o = 16; o; o >>= 1) s += __shfl_xor_sync(0xffffffffu, s, o);
    if (lane == 0) out[e] = 1.f / (1.f + expf(-(s + b3[0])));
}

// ---------------- host orchestration ---------------------------------------
extern "C" void kernel_launch(void* const* d_in, const int* in_sizes, int n_in,
                              void* d_out, int out_size) {
    const float* x     = (const float*)d_in[0];
    const int*   ei    = (const int*)d_in[1];
    const float* Win   = (const float*)d_in[2];
    const float* Wrel  = (const float*)d_in[3];
    const float* brel  = (const float*)d_in[4];
    const float* Wroot = (const float*)d_in[5];
    const float* gamma = (const float*)d_in[6];
    const float* beta  = (const float*)d_in[7];
    const float* W1    = (const float*)d_in[8];
    const float* b1    = (const float*)d_in[9];
    const float* W2    = (const float*)d_in[10];
    const float* b2    = (const float*)d_in[11];
    const float* W3    = (const float*)d_in[12];
    const float* b3    = (const float*)d_in[13];

    int N = in_sizes[0] / 2;
    int E = in_sizes[1] / 2;
    float* out = (float*)d_out;

    // CSR build (per call)
    k_zero_cnt<<<(N + 255) / 256, 256>>>(N);
    k_hist<<<(E + 255) / 256, 256>>>(ei, E);
    k_scan<<<1, 1024>>>(N);
    k_fill<<<(E + 255) / 256, 256>>>(ei, E);

    k_input<<<N, HID>>>(x, Win, N);

    dim3 gN(HID / TBN, (N + TBM - 1) / TBM);
    dim3 gE(HID / TBN, (E + TBM - 1) / TBM);

    for (int l = 0; l < NLAYERS; l++) {
        k_aggr<<<(N + 3) / 4, 256>>>(N);
        k_layer_gemm<<<gN, 256>>>(Wrel + (size_t)l * HID * HID,
                                  Wroot + (size_t)l * HID * HID,
                                  brel + (size_t)l * HID, N);
        k_bn_zero<<<1, HID>>>();
        k_bn_partial<<<(N + 255) / 256, HID>>>(N);
        k_bn_final<<<1, HID>>>(gamma + (size_t)l * HID,
                               beta + (size_t)l * HID, 1.0f / (float)N);
        k_bn_apply<<<N, HID>>>(N);
    }

    k_edge_gemm1<<<gE, 256>>>(ei, E, W1, b1);
    k_edge_gemm2<<<gE, 256>>>(W2, b2, E);
    k_final<<<(E + 7) / 8, 256>>>(W3, b3, out, E);
}

// round 6
// speedup vs baseline: 3.9784x; 3.9784x over previous
#include <cuda_runtime.h>
#include <math.h>
#include <stdint.h>

#define HID 256
#define NLAYERS 15
#define MAXN 50000
#define MAXE 500000
#define EPS 1e-5f

// ---------------- scratch (static device globals) --------------------------
__device__ float g_h[(size_t)MAXN * HID];
__device__ float g_agg[(size_t)MAXN * HID];
__device__ float g_out[(size_t)MAXN * HID];
__device__ float g_z1[(size_t)MAXE * HID];
__device__ float g_z2[(size_t)MAXE * HID];
__device__ float g_sum[HID];
__device__ float g_sq[HID];
__device__ float g_scale[HID];
__device__ float g_shift[HID];
// CSR scratch
__device__ int g_cnt[MAXN];
__device__ int g_rowptr[MAXN + 1];
__device__ int g_cur[MAXN];
__device__ int g_csr[MAXE];

// ---------------- input fc: h = x @ W_in^T (IN_CH=2) -----------------------
__global__ void k_input(const float* __restrict__ x,
                        const float* __restrict__ Win, int N) {
    int i = blockIdx.x;
    int j = threadIdx.x;
    if (i < N)
        g_h[(size_t)i * HID + j] =
            fmaf(x[2 * i], Win[2 * j], x[2 * i + 1] * Win[2 * j + 1]);
}

// ---------------- CSR build ------------------------------------------------
__global__ void k_zero_cnt(int N) {
    int i = blockIdx.x * blockDim.x + threadIdx.x;
    if (i < N) g_cnt[i] = 0;
}
__global__ void k_hist(const int* __restrict__ ei, int E) {
    int e = blockIdx.x * blockDim.x + threadIdx.x;
    if (e < E) atomicAdd(&g_cnt[ei[E + e]], 1);
}
__global__ void k_scan(int N) {
    __shared__ int s[1024];
    int t = threadIdx.x;
    int chunk = (N + 1023) / 1024;
    int lo = t * chunk, hi = min(lo + chunk, N);
    int sum = 0;
    for (int i = lo; i < hi; i++) sum += g_cnt[i];
    s[t] = sum;
    __syncthreads();
    for (int off = 1; off < 1024; off <<= 1) {
        int v = (t >= off) ? s[t - off] : 0;
        __syncthreads();
        s[t] += v;
        __syncthreads();
    }
    int run = (t == 0) ? 0 : s[t - 1];
    for (int i = lo; i < hi; i++) {
        g_rowptr[i] = run;
        g_cur[i] = run;
        run += g_cnt[i];
    }
    if (t == 0) g_rowptr[N] = s[1023];
}
__global__ void k_fill(const int* __restrict__ ei, int E) {
    int e = blockIdx.x * blockDim.x + threadIdx.x;
    if (e < E) {
        int d = ei[E + e];
        int p = atomicAdd(&g_cur[d], 1);
        g_csr[p] = ei[e];
    }
}

// ---------------- CSR aggregate: agg[i] = sum_{e: dst=i} h[src[e]] ---------
__global__ void __launch_bounds__(256) k_aggr(int N) {
    int node = blockIdx.x * 4 + (threadIdx.x >> 6);
    int lane = threadIdx.x & 63;
    if (node >= N) return;
    int s = g_rowptr[node], e = g_rowptr[node + 1];
    float4 acc = make_float4(0.f, 0.f, 0.f, 0.f);
    for (int i = s; i < e; i++) {
        int src = g_csr[i];
        float4 v = *reinterpret_cast<const float4*>(
            g_h + (size_t)src * HID + lane * 4);
        acc.x += v.x; acc.y += v.y; acc.z += v.z; acc.w += v.w;
    }
    *reinterpret_cast<float4*>(g_agg + (size_t)node * HID + lane * 4) = acc;
}

// ================= tf32 tensor-core GEMM machinery =========================
#define BM 128
#define BN 128
#define BK 32
#define LDS_S 36          // row stride in floats (BK + 4 pad) -> conflict-free

__device__ __forceinline__ unsigned f2tf(float f) {
    unsigned u;
    asm("cvt.rna.tf32.f32 %0, %1;" : "=r"(u) : "f"(f));
    return u;
}

__device__ __forceinline__ void mma8(float* c, const unsigned* a,
                                     const unsigned* b) {
    asm volatile(
        "mma.sync.aligned.m16n8k8.row.col.f32.tf32.tf32.f32 "
        "{%0,%1,%2,%3}, {%4,%5,%6,%7}, {%8,%9}, {%0,%1,%2,%3};"
        : "+f"(c[0]), "+f"(c[1]), "+f"(c[2]), "+f"(c[3])
        : "r"(a[0]), "r"(a[1]), "r"(a[2]), "r"(a[3]), "r"(b[0]), "r"(b[1]));
}

// load one 128x32 tile from row-major src (row clamped) into smem as tf32
__device__ __forceinline__ void load_tile(const float* __restrict__ src,
                                          int row0, int maxrow, int ldk,
                                          int kbase, unsigned* s, int tid) {
    int r = tid >> 1;
    int gr = min(row0 + r, maxrow - 1);
    const float* p = src + (size_t)gr * ldk + kbase + (tid & 1) * 16;
    unsigned* d = s + r * LDS_S + (tid & 1) * 16;
#pragma unroll
    for (int q = 0; q < 4; q++) {
        float4 v = *reinterpret_cast<const float4*>(p + q * 4);
        uint4 u;
        u.x = f2tf(v.x); u.y = f2tf(v.y); u.z = f2tf(v.z); u.w = f2tf(v.w);
        *reinterpret_cast<uint4*>(d + q * 4) = u;
    }
}

// one BK stage of warp MMAs (warp tile 64x32: 4 m-tiles x 4 n-tiles)
__device__ __forceinline__ void stage_mma(const unsigned* sA,
                                          const unsigned* sB, int wm, int wn,
                                          int lane, float acc[4][4][4]) {
#pragma unroll
    for (int ks = 0; ks < BK / 8; ks++) {
        unsigned a[4][4], b[4][2];
        int col = ks * 8 + (lane & 3);
#pragma unroll
        for (int mt = 0; mt < 4; mt++) {
            int row = wm * 64 + mt * 16 + (lane >> 2);
            const unsigned* p = sA + row * LDS_S + col;
            a[mt][0] = p[0];
            a[mt][1] = p[8 * LDS_S];
            a[mt][2] = p[4];
            a[mt][3] = p[8 * LDS_S + 4];
        }
#pragma unroll
        for (int nt = 0; nt < 4; nt++) {
            int n = wn * 32 + nt * 8 + (lane >> 2);
            const unsigned* p = sB + n * LDS_S + col;
            b[nt][0] = p[0];
            b[nt][1] = p[4];
        }
#pragma unroll
        for (int mt = 0; mt < 4; mt++)
#pragma unroll
            for (int nt = 0; nt < 4; nt++)
                mma8(acc[mt][nt], a[mt], b[nt]);
    }
}

// ---------- node layer: g_out = agg @ Wrel^T + h @ Wroot^T + brel ----------
__global__ void __launch_bounds__(256, 2)
k_gemm_node(const float* __restrict__ Wrel, const float* __restrict__ Wroot,
            const float* __restrict__ brel, int M) {
    __shared__ unsigned sA[BM * LDS_S];
    __shared__ unsigned sB[BN * LDS_S];
    int tid = threadIdx.x, lane = tid & 31, wid = tid >> 5;
    int wm = wid >> 2, wn = wid & 3;
    int bm = blockIdx.y * BM, bn = blockIdx.x * BN;

    float acc[4][4][4] = {};

#pragma unroll 1
    for (int seg = 0; seg < 2; seg++) {
        const float* A = seg ? g_h : g_agg;
        const float* W = seg ? Wroot : Wrel;
#pragma unroll 1
        for (int k0 = 0; k0 < HID; k0 += BK) {
            load_tile(A, bm, M, HID, k0, sA, tid);
            load_tile(W, bn, HID, HID, k0, sB, tid);
            __syncthreads();
            stage_mma(sA, sB, wm, wn, lane, acc);
            __syncthreads();
        }
    }

#pragma unroll
    for (int mt = 0; mt < 4; mt++) {
        int r0 = bm + wm * 64 + mt * 16 + (lane >> 2);
#pragma unroll
        for (int nt = 0; nt < 4; nt++) {
            int c = bn + wn * 32 + nt * 8 + 2 * (lane & 3);
            float b0 = brel[c], b1 = brel[c + 1];
            if (r0 < M) {
                float2 o = {acc[mt][nt][0] + b0, acc[mt][nt][1] + b1};
                *reinterpret_cast<float2*>(g_out + (size_t)r0 * HID + c) = o;
            }
            if (r0 + 8 < M) {
                float2 o = {acc[mt][nt][2] + b0, acc[mt][nt][3] + b1};
                *reinterpret_cast<float2*>(g_out + (size_t)(r0 + 8) * HID + c) = o;
            }
        }
    }
}

// ---------- edge hidden-1: z1 = relu(cat(h[src],h[dst]) @ W1^T + b1) -------
__global__ void __launch_bounds__(256, 2)
k_gemm_edge1(const int* __restrict__ ei, int E, const float* __restrict__ W1,
             const float* __restrict__ b1) {
    __shared__ unsigned sA[BM * LDS_S];
    __shared__ unsigned sB[BN * LDS_S];
    int tid = threadIdx.x, lane = tid & 31, wid = tid >> 5;
    int wm = wid >> 2, wn = wid & 3;
    int bm = blockIdx.y * BM, bn = blockIdx.x * BN;

    // loader thread's fixed edge
    int e = min(bm + (tid >> 1), E - 1);
    int nsrc = ei[e], ndst = ei[E + e];

    float acc[4][4][4] = {};

#pragma unroll 1
    for (int k0 = 0; k0 < 2 * HID; k0 += BK) {
        // gather A tile: rows = edges, cols = concat(h[src], h[dst])
        {
            int kg = k0 + (tid & 1) * 16;
            int node = (kg < HID) ? nsrc : ndst;
            const float* p = g_h + (size_t)node * HID + (kg & (HID - 1));
            unsigned* d = sA + (tid >> 1) * LDS_S + (tid & 1) * 16;
#pragma unroll
            for (int q = 0; q < 4; q++) {
                float4 v = *reinterpret_cast<const float4*>(p + q * 4);
                uint4 u;
                u.x = f2tf(v.x); u.y = f2tf(v.y);
                u.z = f2tf(v.z); u.w = f2tf(v.w);
                *reinterpret_cast<uint4*>(d + q * 4) = u;
            }
        }
        load_tile(W1, bn, HID, 2 * HID, k0, sB, tid);
        __syncthreads();
        stage_mma(sA, sB, wm, wn, lane, acc);
        __syncthreads();
    }

#pragma unroll
    for (int mt = 0; mt < 4; mt++) {
        int r0 = bm + wm * 64 + mt * 16 + (lane >> 2);
#pragma unroll
        for (int nt = 0; nt < 4; nt++) {
            int c = bn + wn * 32 + nt * 8 + 2 * (lane & 3);
            float bb0 = b1[c], bb1 = b1[c + 1];
            if (r0 < E) {
                float2 o = {fmaxf(acc[mt][nt][0] + bb0, 0.f),
                            fmaxf(acc[mt][nt][1] + bb1, 0.f)};
                *reinterpret_cast<float2*>(g_z1 + (size_t)r0 * HID + c) = o;
            }
            if (r0 + 8 < E) {
                float2 o = {fmaxf(acc[mt][nt][2] + bb0, 0.f),
                            fmaxf(acc[mt][nt][3] + bb1, 0.f)};
                *reinterpret_cast<float2*>(g_z1 + (size_t)(r0 + 8) * HID + c) = o;
            }
        }
    }
}

// ---------- edge hidden-2: z2 = relu(z1 @ W2^T + b2) -----------------------
__global__ void __launch_bounds__(256, 2)
k_gemm_edge2(const float* __restrict__ W2, const float* __restrict__ b2,
             int E) {
    __shared__ unsigned sA[BM * LDS_S];
    __shared__ unsigned sB[BN * LDS_S];
    int tid = threadIdx.x, lane = tid & 31, wid = tid >> 5;
    int wm = wid >> 2, wn = wid & 3;
    int bm = blockIdx.y * BM, bn = blockIdx.x * BN;

    float acc[4][4][4] = {};

#pragma unroll 1
    for (int k0 = 0; k0 < HID; k0 += BK) {
        load_tile(g_z1, bm, E, HID, k0, sA, tid);
        load_tile(W2, bn, HID, HID, k0, sB, tid);
        __syncthreads();
        stage_mma(sA, sB, wm, wn, lane, acc);
        __syncthreads();
    }

#pragma unroll
    for (int mt = 0; mt < 4; mt++) {
        int r0 = bm + wm * 64 + mt * 16 + (lane >> 2);
#pragma unroll
        for (int nt = 0; nt < 4; nt++) {
            int c = bn + wn * 32 + nt * 8 + 2 * (lane & 3);
            float bb0 = b2[c], bb1 = b2[c + 1];
            if (r0 < E) {
                float2 o = {fmaxf(acc[mt][nt][0] + bb0, 0.f),
                            fmaxf(acc[mt][nt][1] + bb1, 0.f)};
                *reinterpret_cast<float2*>(g_z2 + (size_t)r0 * HID + c) = o;
            }
            if (r0 + 8 < E) {
                float2 o = {fmaxf(acc[mt][nt][2] + bb0, 0.f),
                            fmaxf(acc[mt][nt][3] + bb1, 0.f)};
                *reinterpret_cast<float2*>(g_z2 + (size_t)(r0 + 8) * HID + c) = o;
            }
        }
    }
}

// ---------------- batchnorm ------------------------------------------------
__global__ void k_bn_zero() {
    int c = threadIdx.x;
    g_sum[c] = 0.f;
    g_sq[c] = 0.f;
}
__global__ void k_bn_partial(int N) {
    int c = threadIdx.x;
    int r0 = blockIdx.x * 256;
    int r1 = min(r0 + 256, N);
    float s = 0.f, q = 0.f;
    for (int r = r0; r < r1; r++) {
        float v = g_out[(size_t)r * HID + c];
        s += v;
        q = fmaf(v, v, q);
    }
    atomicAdd(&g_sum[c], s);
    atomicAdd(&g_sq[c], q);
}
__global__ void k_bn_final(const float* __restrict__ gamma,
                           const float* __restrict__ beta, float invN) {
    int c = threadIdx.x;
    float m = g_sum[c] * invN;
    float var = g_sq[c] * invN - m * m;
    float rstd = rsqrtf(var + EPS);
    float sc = rstd * gamma[c];
    g_scale[c] = sc;
    g_shift[c] = beta[c] - m * sc;
}
__global__ void k_bn_apply(int N) {
    int i = blockIdx.x, c = threadIdx.x;
    size_t idx = (size_t)i * HID + c;
    float v = fmaf(g_out[idx], g_scale[c], g_shift[c]);
    g_h[idx] += fmaxf(v, 0.f);
}

// ---------------- final: sigmoid(z2 @ W3^T + b3) ---------------------------
__global__ void k_final(const float* __restrict__ W3,
                        const float* __restrict__ b3,
                        float* __restrict__ out, int E) {
    int w = threadIdx.x >> 5, lane = threadIdx.x & 31;
    int e = blockIdx.x * 8 + w;
    if (e >= E) return;
    const float* z = g_z2 + (size_t)e * HID;
    float s = 0.f;
#pragma unroll
    for (int i = 0; i < 8; i++)
        s = fmaf(z[lane + 32 * i], W3[lane + 32 * i], s);
#pragma unroll
    for (int o = 16; o; o >>= 1) s += __shfl_xor_sync(0xffffffffu, s, o);
    if (lane == 0) out[e] = 1.f / (1.f + expf(-(s + b3[0])));
}

// ---------------- host orchestration ---------------------------------------
extern "C" void kernel_launch(void* const* d_in, const int* in_sizes, int n_in,
                              void* d_out, int out_size) {
    const float* x     = (const float*)d_in[0];
    const int*   ei    = (const int*)d_in[1];
    const float* Win   = (const float*)d_in[2];
    const float* Wrel  = (const float*)d_in[3];
    const float* brel  = (const float*)d_in[4];
    const float* Wroot = (const float*)d_in[5];
    const float* gamma = (const float*)d_in[6];
    const float* beta  = (const float*)d_in[7];
    const float* W1    = (const float*)d_in[8];
    const float* b1    = (const float*)d_in[9];
    const float* W2    = (const float*)d_in[10];
    const float* b2    = (const float*)d_in[11];
    const float* W3    = (const float*)d_in[12];
    const float* b3    = (const float*)d_in[13];

    int N = in_sizes[0] / 2;
    int E = in_sizes[1] / 2;
    float* out = (float*)d_out;

    // CSR build
    k_zero_cnt<<<(N + 255) / 256, 256>>>(N);
    k_hist<<<(E + 255) / 256, 256>>>(ei, E);
    k_scan<<<1, 1024>>>(N);
    k_fill<<<(E + 255) / 256, 256>>>(ei, E);

    k_input<<<N, HID>>>(x, Win, N);

    dim3 gN(HID / BN, (N + BM - 1) / BM);
    dim3 gE(HID / BN, (E + BM - 1) / BM);

    for (int l = 0; l < NLAYERS; l++) {
        k_aggr<<<(N + 3) / 4, 256>>>(N);
        k_gemm_node<<<gN, 256>>>(Wrel + (size_t)l * HID * HID,
                                 Wroot + (size_t)l * HID * HID,
                                 brel + (size_t)l * HID, N);
        k_bn_zero<<<1, HID>>>();
        k_bn_partial<<<(N + 255) / 256, HID>>>(N);
        k_bn_final<<<1, HID>>>(gamma + (size_t)l * HID,
                               beta + (size_t)l * HID, 1.0f / (float)N);
        k_bn_apply<<<N, HID>>>(N);
    }

    k_gemm_edge1<<<gE, 256>>>(ei, E, W1, b1);
    k_gemm_edge2<<<gE, 256>>>(W2, b2, E);
    k_final<<<(E + 7) / 8, 256>>>(W3, b3, out, E);
}

// round 7
// speedup vs baseline: 4.4052x; 1.1073x over previous
#include <cuda_runtime.h>
#include <math.h>
#include <stdint.h>

#define HID 256
#define NLAYERS 15
#define MAXN 50000
#define MAXE 500000
#define EPS 1e-5f

// ---------------- scratch (static device globals) --------------------------
__device__ float g_h[(size_t)MAXN * HID];
__device__ float g_agg[(size_t)MAXN * HID];
__device__ float g_out[(size_t)MAXN * HID];
__device__ float g_sum[HID];
__device__ float g_sq[HID];
__device__ float g_scale[HID];
__device__ float g_shift[HID];
// CSR scratch
__device__ int g_cnt[MAXN];
__device__ int g_rowptr[MAXN + 1];
__device__ int g_cur[MAXN];
__device__ int g_csr[MAXE];

// ---------------- input fc: h = x @ W_in^T (IN_CH=2) -----------------------
__global__ void k_input(const float* __restrict__ x,
                        const float* __restrict__ Win, int N) {
    int i = blockIdx.x;
    int j = threadIdx.x;
    if (i < N)
        g_h[(size_t)i * HID + j] =
            fmaf(x[2 * i], Win[2 * j], x[2 * i + 1] * Win[2 * j + 1]);
}

// ---------------- CSR build ------------------------------------------------
__global__ void k_zero_cnt(int N) {
    int i = blockIdx.x * blockDim.x + threadIdx.x;
    if (i < N) g_cnt[i] = 0;
}
__global__ void k_hist(const int* __restrict__ ei, int E) {
    int e = blockIdx.x * blockDim.x + threadIdx.x;
    if (e < E) atomicAdd(&g_cnt[ei[E + e]], 1);
}
__global__ void k_scan(int N) {
    __shared__ int s[1024];
    int t = threadIdx.x;
    int chunk = (N + 1023) / 1024;
    int lo = t * chunk, hi = min(lo + chunk, N);
    int sum = 0;
    for (int i = lo; i < hi; i++) sum += g_cnt[i];
    s[t] = sum;
    __syncthreads();
    for (int off = 1; off < 1024; off <<= 1) {
        int v = (t >= off) ? s[t - off] : 0;
        __syncthreads();
        s[t] += v;
        __syncthreads();
    }
    int run = (t == 0) ? 0 : s[t - 1];
    for (int i = lo; i < hi; i++) {
        g_rowptr[i] = run;
        g_cur[i] = run;
        run += g_cnt[i];
    }
    if (t == 0) g_rowptr[N] = s[1023];
}
__global__ void k_fill(const int* __restrict__ ei, int E) {
    int e = blockIdx.x * blockDim.x + threadIdx.x;
    if (e < E) {
        int d = ei[E + e];
        int p = atomicAdd(&g_cur[d], 1);
        g_csr[p] = ei[e];
    }
}

// ---------------- CSR aggregate: agg[i] = sum_{e: dst=i} h[src[e]] ---------
__global__ void __launch_bounds__(256) k_aggr(int N) {
    int node = blockIdx.x * 4 + (threadIdx.x >> 6);
    int lane = threadIdx.x & 63;
    if (node >= N) return;
    int s = g_rowptr[node], e = g_rowptr[node + 1];
    float4 acc = make_float4(0.f, 0.f, 0.f, 0.f);
    for (int i = s; i < e; i++) {
        int src = g_csr[i];
        float4 v = *reinterpret_cast<const float4*>(
            g_h + (size_t)src * HID + lane * 4);
        acc.x += v.x; acc.y += v.y; acc.z += v.z; acc.w += v.w;
    }
    *reinterpret_cast<float4*>(g_agg + (size_t)node * HID + lane * 4) = acc;
}

// ================= tf32 tensor-core GEMM machinery =========================
#define BM 128
#define BN 128
#define BK 32
#define LDS_S 36          // smem row stride (conflict-free)

__device__ __forceinline__ unsigned f2tf(float f) {
    unsigned u;
    asm("cvt.rna.tf32.f32 %0, %1;" : "=r"(u) : "f"(f));
    return u;
}

__device__ __forceinline__ void mma8(float* c, const unsigned* a,
                                     const unsigned* b) {
    asm volatile(
        "mma.sync.aligned.m16n8k8.row.col.f32.tf32.tf32.f32 "
        "{%0,%1,%2,%3}, {%4,%5,%6,%7}, {%8,%9}, {%0,%1,%2,%3};"
        : "+f"(c[0]), "+f"(c[1]), "+f"(c[2]), "+f"(c[3])
        : "r"(a[0]), "r"(a[1]), "r"(a[2]), "r"(a[3]), "r"(b[0]), "r"(b[1]));
}

// load a (rows x 32) tile from row-major src (row clamped) into smem as tf32
// covers 2*blockDim rows-of-halves: thread t -> row t>>1, 16-col half (t&1)
__device__ __forceinline__ void load_tile(const float* __restrict__ src,
                                          int row0, int maxrow, int ldk,
                                          int kbase, unsigned* s, int tid) {
    int r = tid >> 1;
    int gr = min(row0 + r, maxrow - 1);
    const float* p = src + (size_t)gr * ldk + kbase + (tid & 1) * 16;
    unsigned* d = s + r * LDS_S + (tid & 1) * 16;
#pragma unroll
    for (int q = 0; q < 4; q++) {
        float4 v = *reinterpret_cast<const float4*>(p + q * 4);
        uint4 u;
        u.x = f2tf(v.x); u.y = f2tf(v.y); u.z = f2tf(v.z); u.w = f2tf(v.w);
        *reinterpret_cast<uint4*>(d + q * 4) = u;
    }
}

// one BK=32 stage, 8-warp (2x4) layout, warp tile 64x32
__device__ __forceinline__ void stage_mma(const unsigned* sA,
                                          const unsigned* sB, int wm, int wn,
                                          int lane, float acc[4][4][4]) {
#pragma unroll
    for (int ks = 0; ks < BK / 8; ks++) {
        unsigned a[4][4], b[4][2];
        int col = ks * 8 + (lane & 3);
#pragma unroll
        for (int mt = 0; mt < 4; mt++) {
            int row = wm * 64 + mt * 16 + (lane >> 2);
            const unsigned* p = sA + row * LDS_S + col;
            a[mt][0] = p[0];
            a[mt][1] = p[8 * LDS_S];
            a[mt][2] = p[4];
            a[mt][3] = p[8 * LDS_S + 4];
        }
#pragma unroll
        for (int nt = 0; nt < 4; nt++) {
            int n = wn * 32 + nt * 8 + (lane >> 2);
            const unsigned* p = sB + n * LDS_S + col;
            b[nt][0] = p[0];
            b[nt][1] = p[4];
        }
#pragma unroll
        for (int mt = 0; mt < 4; mt++)
#pragma unroll
            for (int nt = 0; nt < 4; nt++)
                mma8(acc[mt][nt], a[mt], b[nt]);
    }
}

// ---------- node layer: g_out = agg @ Wrel^T + h @ Wroot^T + brel ----------
// epilogue also accumulates per-column sum / sumsq into g_sum / g_sq.
__global__ void __launch_bounds__(256, 2)
k_gemm_node(const float* __restrict__ Wrel, const float* __restrict__ Wroot,
            const float* __restrict__ brel, int M) {
    __shared__ unsigned sA[BM * LDS_S];
    __shared__ unsigned sB[BN * LDS_S];
    int tid = threadIdx.x, lane = tid & 31, wid = tid >> 5;
    int wm = wid >> 2, wn = wid & 3;
    int bm = blockIdx.y * BM, bn = blockIdx.x * BN;

    float acc[4][4][4] = {};

#pragma unroll 1
    for (int seg = 0; seg < 2; seg++) {
        const float* A = seg ? g_h : g_agg;
        const float* W = seg ? Wroot : Wrel;
#pragma unroll 1
        for (int k0 = 0; k0 < HID; k0 += BK) {
            load_tile(A, bm, M, HID, k0, sA, tid);
            load_tile(W, bn, HID, HID, k0, sB, tid);
            __syncthreads();
            stage_mma(sA, sB, wm, wn, lane, acc);
            __syncthreads();
        }
    }

    // write + fused BN statistics
#pragma unroll
    for (int nt = 0; nt < 4; nt++) {
        int c = bn + wn * 32 + nt * 8 + 2 * (lane & 3);
        float b0 = brel[c], b1 = brel[c + 1];
        float s0 = 0.f, s1 = 0.f, q0 = 0.f, q1 = 0.f;
#pragma unroll
        for (int mt = 0; mt < 4; mt++) {
            int r0 = bm + wm * 64 + mt * 16 + (lane >> 2);
            if (r0 < M) {
                float v0 = acc[mt][nt][0] + b0;
                float v1 = acc[mt][nt][1] + b1;
                *reinterpret_cast<float2*>(g_out + (size_t)r0 * HID + c) =
                    make_float2(v0, v1);
                s0 += v0; q0 = fmaf(v0, v0, q0);
                s1 += v1; q1 = fmaf(v1, v1, q1);
            }
            if (r0 + 8 < M) {
                float v0 = acc[mt][nt][2] + b0;
                float v1 = acc[mt][nt][3] + b1;
                *reinterpret_cast<float2*>(g_out + (size_t)(r0 + 8) * HID + c) =
                    make_float2(v0, v1);
                s0 += v0; q0 = fmaf(v0, v0, q0);
                s1 += v1; q1 = fmaf(v1, v1, q1);
            }
        }
#pragma unroll
        for (int off = 4; off < 32; off <<= 1) {
            s0 += __shfl_xor_sync(0xffffffffu, s0, off);
            s1 += __shfl_xor_sync(0xffffffffu, s1, off);
            q0 += __shfl_xor_sync(0xffffffffu, q0, off);
            q1 += __shfl_xor_sync(0xffffffffu, q1, off);
        }
        if (lane < 4) {
            atomicAdd(&g_sum[c], s0);
            atomicAdd(&g_sum[c + 1], s1);
            atomicAdd(&g_sq[c], q0);
            atomicAdd(&g_sq[c + 1], q1);
        }
    }
}

// ================= fused edge MLP ==========================================
// one CTA: 128 edges, full 256-wide MLP, z1 kept in smem, direct sigmoid out.
#define ETM 128
#define Z1S 260   // z1 smem row stride (260 mod 32 = 4 -> conflict-free)

// 16-warp (4x4) stage: warp tile 32x64, acc[2][8][4]
__device__ __forceinline__ void stage_mma16(const unsigned* sA, int ldA,
                                            int kA0, const unsigned* sB,
                                            int wm, int wn, int lane,
                                            float acc[2][8][4]) {
#pragma unroll
    for (int ks = 0; ks < 4; ks++) {
        unsigned a[2][4], b[8][2];
        int colA = kA0 + ks * 8 + (lane & 3);
        int colB = ks * 8 + (lane & 3);
#pragma unroll
        for (int mt = 0; mt < 2; mt++) {
            int row = wm * 32 + mt * 16 + (lane >> 2);
            const unsigned* p = sA + row * ldA + colA;
            a[mt][0] = p[0];
            a[mt][1] = p[8 * ldA];
            a[mt][2] = p[4];
            a[mt][3] = p[8 * ldA + 4];
        }
#pragma unroll
        for (int nt = 0; nt < 8; nt++) {
            int n = wn * 64 + nt * 8 + (lane >> 2);
            const unsigned* p = sB + n * LDS_S + colB;
            b[nt][0] = p[0];
            b[nt][1] = p[4];
        }
#pragma unroll
        for (int mt = 0; mt < 2; mt++)
#pragma unroll
            for (int nt = 0; nt < 8; nt++)
                mma8(acc[mt][nt], a[mt], b[nt]);
    }
}

__global__ void __launch_bounds__(512, 1)
k_edge_fused(const int* __restrict__ ei, int E,
             const float* __restrict__ W1, const float* __restrict__ b1,
             const float* __restrict__ W2, const float* __restrict__ b2,
             const float* __restrict__ W3, const float* __restrict__ b3,
             float* __restrict__ out) {
    extern __shared__ unsigned esm[];
    unsigned* sA = esm;                       // 128*36
    unsigned* sB = sA + ETM * LDS_S;          // 256*36
    unsigned* z1s = sB + 256 * LDS_S;         // 128*260
    float* sdot = (float*)(z1s + ETM * Z1S);  // 128

    int tid = threadIdx.x, lane = tid & 31, wid = tid >> 5;
    int wm = wid >> 2, wn = wid & 3;
    int bm = blockIdx.x * ETM;

    if (tid < ETM) sdot[tid] = 0.f;

    // loader: thread covers edge (tid>>2), 8-col segment (tid&3)*8
    int e = min(bm + (tid >> 2), E - 1);
    int nsrc = ei[e], ndst = ei[E + e];

    float acc[2][8][4] = {};

    // ---- stage 1: z1 = relu(cat(h[src],h[dst]) @ W1^T + b1), K = 512 ------
#pragma unroll 1
    for (int k0 = 0; k0 < 2 * HID; k0 += BK) {
        {
            int kg = k0 + (tid & 3) * 8;
            int node = (kg < HID) ? nsrc : ndst;
            const float* p = g_h + (size_t)node * HID + (kg & (HID - 1));
            unsigned* d = sA + (tid >> 2) * LDS_S + (tid & 3) * 8;
#pragma unroll
            for (int q = 0; q < 2; q++) {
                float4 v = *reinterpret_cast<const float4*>(p + q * 4);
                uint4 u;
                u.x = f2tf(v.x); u.y = f2tf(v.y);
                u.z = f2tf(v.z); u.w = f2tf(v.w);
                *reinterpret_cast<uint4*>(d + q * 4) = u;
            }
        }
        load_tile(W1, 0, HID, 2 * HID, k0, sB, tid);
        __syncthreads();
        stage_mma16(sA, LDS_S, 0, sB, wm, wn, lane, acc);
        __syncthreads();
    }

    // store z1 (bias+relu, tf32) into smem; zero acc for stage 2
#pragma unroll
    for (int mt = 0; mt < 2; mt++) {
        int r0 = wm * 32 + mt * 16 + (lane >> 2);
#pragma unroll
        for (int nt = 0; nt < 8; nt++) {
            int c = wn * 64 + nt * 8 + 2 * (lane & 3);
            float bb0 = b1[c], bb1 = b1[c + 1];
            uint2 u0, u1;
            u0.x = f2tf(fmaxf(acc[mt][nt][0] + bb0, 0.f));
            u0.y = f2tf(fmaxf(acc[mt][nt][1] + bb1, 0.f));
            u1.x = f2tf(fmaxf(acc[mt][nt][2] + bb0, 0.f));
            u1.y = f2tf(fmaxf(acc[mt][nt][3] + bb1, 0.f));
            *reinterpret_cast<uint2*>(z1s + r0 * Z1S + c) = u0;
            *reinterpret_cast<uint2*>(z1s + (r0 + 8) * Z1S + c) = u1;
#pragma unroll
            for (int q = 0; q < 4; q++) acc[mt][nt][q] = 0.f;
        }
    }

    // ---- stage 2: z2 = relu(z1 @ W2^T + b2), K = 256, A from smem ---------
#pragma unroll 1
    for (int k0 = 0; k0 < HID; k0 += BK) {
        load_tile(W2, 0, HID, HID, k0, sB, tid);
        __syncthreads();   // also orders z1s stores on first iteration
        stage_mma16(z1s, Z1S, k0, sB, wm, wn, lane, acc);
        __syncthreads();
    }

    // ---- stage 3: per-edge dot with W3 + sigmoid --------------------------
    float part[2][2] = {};
#pragma unroll
    for (int mt = 0; mt < 2; mt++) {
#pragma unroll
        for (int nt = 0; nt < 8; nt++) {
            int c = wn * 64 + nt * 8 + 2 * (lane & 3);
            float bb0 = b2[c], bb1 = b2[c + 1];
            float w0 = W3[c], w1 = W3[c + 1];
            float z0 = fmaxf(acc[mt][nt][0] + bb0, 0.f);
            float z1v = fmaxf(acc[mt][nt][1] + bb1, 0.f);
            float z2v = fmaxf(acc[mt][nt][2] + bb0, 0.f);
            float z3 = fmaxf(acc[mt][nt][3] + bb1, 0.f);
            part[mt][0] = fmaf(z0, w0, fmaf(z1v, w1, part[mt][0]));
            part[mt][1] = fmaf(z2v, w0, fmaf(z3, w1, part[mt][1]));
        }
    }
#pragma unroll
    for (int off = 1; off < 4; off <<= 1) {
        part[0][0] += __shfl_xor_sync(0xffffffffu, part[0][0], off);
        part[0][1] += __shfl_xor_sync(0xffffffffu, part[0][1], off);
        part[1][0] += __shfl_xor_sync(0xffffffffu, part[1][0], off);
        part[1][1] += __shfl_xor_sync(0xffffffffu, part[1][1], off);
    }
    if ((lane & 3) == 0) {
#pragma unroll
        for (int mt = 0; mt < 2; mt++) {
            int r0 = wm * 32 + mt * 16 + (lane >> 2);
            atomicAdd(&sdot[r0], part[mt][0]);
            atomicAdd(&sdot[r0 + 8], part[mt][1]);
        }
    }
    __syncthreads();
    if (tid < ETM) {
        int eo = bm + tid;
        if (eo < E)
            out[eo] = 1.f / (1.f + expf(-(sdot[tid] + b3[0])));
    }
}

// ---------------- batchnorm ------------------------------------------------
__global__ void k_bn_zero() {
    int c = threadIdx.x;
    g_sum[c] = 0.f;
    g_sq[c] = 0.f;
}
__global__ void k_bn_final(const float* __restrict__ gamma,
                           const float* __restrict__ beta, float invN) {
    int c = threadIdx.x;
    float m = g_sum[c] * invN;
    float var = g_sq[c] * invN - m * m;
    float rstd = rsqrtf(var + EPS);
    float sc = rstd * gamma[c];
    g_scale[c] = sc;
    g_shift[c] = beta[c] - m * sc;
}
__global__ void k_bn_apply(int N) {
    int i = blockIdx.x, c = threadIdx.x;
    size_t idx = (size_t)i * HID + c;
    float v = fmaf(g_out[idx], g_scale[c], g_shift[c]);
    g_h[idx] += fmaxf(v, 0.f);
}

// ---------------- host orchestration ---------------------------------------
extern "C" void kernel_launch(void* const* d_in, const int* in_sizes, int n_in,
                              void* d_out, int out_size) {
    const float* x     = (const float*)d_in[0];
    const int*   ei    = (const int*)d_in[1];
    const float* Win   = (const float*)d_in[2];
    const float* Wrel  = (const float*)d_in[3];
    const float* brel  = (const float*)d_in[4];
    const float* Wroot = (const float*)d_in[5];
    const float* gamma = (const float*)d_in[6];
    const float* beta  = (const float*)d_in[7];
    const float* W1    = (const float*)d_in[8];
    const float* b1    = (const float*)d_in[9];
    const float* W2    = (const float*)d_in[10];
    const float* b2    = (const float*)d_in[11];
    const float* W3    = (const float*)d_in[12];
    const float* b3    = (const float*)d_in[13];

    int N = in_sizes[0] / 2;
    int E = in_sizes[1] / 2;
    float* out = (float*)d_out;

    static const size_t esmem =
        (ETM * LDS_S + 256 * LDS_S + (size_t)ETM * Z1S) * 4 + ETM * 4;
    cudaFuncSetAttribute(k_edge_fused,
                         cudaFuncAttributeMaxDynamicSharedMemorySize,
                         (int)esmem);

    // CSR build
    k_zero_cnt<<<(N + 255) / 256, 256>>>(N);
    k_hist<<<(E + 255) / 256, 256>>>(ei, E);
    k_scan<<<1, 1024>>>(N);
    k_fill<<<(E + 255) / 256, 256>>>(ei, E);

    k_input<<<N, HID>>>(x, Win, N);

    dim3 gN(HID / BN, (N + BM - 1) / BM);

    for (int l = 0; l < NLAYERS; l++) {
        k_aggr<<<(N + 3) / 4, 256>>>(N);
        k_bn_zero<<<1, HID>>>();
        k_gemm_node<<<gN, 256>>>(Wrel + (size_t)l * HID * HID,
                                 Wroot + (size_t)l * HID * HID,
                                 brel + (size_t)l * HID, N);
        k_bn_final<<<1, HID>>>(gamma + (size_t)l * HID,
                               beta + (size_t)l * HID, 1.0f / (float)N);
        k_bn_apply<<<N, HID>>>(N);
    }

    k_edge_fused<<<(E + ETM - 1) / ETM, 512, esmem>>>(ei, E, W1, b1, W2, b2,
                                                      W3, b3, out);
}

// round 8
// speedup vs baseline: 4.4761x; 1.0161x over previous
#include <cuda_runtime.h>
#include <math.h>
#include <stdint.h>

#define HID 256
#define NLAYERS 15
#define MAXN 50000
#define MAXE 500000
#define EPS 1e-5f

// ---------------- scratch (static device globals) --------------------------
__device__ float g_h[(size_t)MAXN * HID];
__device__ unsigned g_htf[(size_t)MAXN * HID];     // tf32 mirror of g_h
__device__ unsigned g_aggtf[(size_t)MAXN * HID];   // tf32 aggregation
__device__ float g_out[(size_t)MAXN * HID];
__device__ float g_sum[HID];
__device__ float g_sq[HID];
// pre-converted tf32 weights
__device__ unsigned g_wrel_tf[NLAYERS * HID * HID];
__device__ unsigned g_wroot_tf[NLAYERS * HID * HID];
__device__ unsigned g_w1tf[2 * HID * HID];
__device__ unsigned g_w2tf[HID * HID];
// CSR scratch
__device__ int g_cnt[MAXN];
__device__ int g_rowptr[MAXN + 1];
__device__ int g_cur[MAXN];
__device__ int g_csr[MAXE];

__device__ __forceinline__ unsigned f2tf(float f) {
    unsigned u;
    asm("cvt.rna.tf32.f32 %0, %1;" : "=r"(u) : "f"(f));
    return u;
}

// ---------------- weight pre-conversion ------------------------------------
__global__ void k_prep(const float* __restrict__ Wrel,
                       const float* __restrict__ Wroot,
                       const float* __restrict__ W1,
                       const float* __restrict__ W2) {
    int i = blockIdx.x * 256 + threadIdx.x;
    const int NW = NLAYERS * HID * HID;
    if (i < NW) {
        g_wrel_tf[i] = f2tf(Wrel[i]);
        g_wroot_tf[i] = f2tf(Wroot[i]);
    }
    if (i < 2 * HID * HID) g_w1tf[i] = f2tf(W1[i]);
    if (i < HID * HID) g_w2tf[i] = f2tf(W2[i]);
}

// ---------------- input fc: h = x @ W_in^T (IN_CH=2) -----------------------
__global__ void k_input(const float* __restrict__ x,
                        const float* __restrict__ Win, int N) {
    int i = blockIdx.x;
    int j = threadIdx.x;
    if (i < N) {
        float v = fmaf(x[2 * i], Win[2 * j], x[2 * i + 1] * Win[2 * j + 1]);
        g_h[(size_t)i * HID + j] = v;
        g_htf[(size_t)i * HID + j] = f2tf(v);
    }
}

// ---------------- CSR build ------------------------------------------------
__global__ void k_zero_cnt(int N) {
    int i = blockIdx.x * blockDim.x + threadIdx.x;
    if (i < N) g_cnt[i] = 0;
}
__global__ void k_hist(const int* __restrict__ ei, int E) {
    int e = blockIdx.x * blockDim.x + threadIdx.x;
    if (e < E) atomicAdd(&g_cnt[ei[E + e]], 1);
}
__global__ void k_scan(int N) {
    __shared__ int s[1024];
    int t = threadIdx.x;
    int chunk = (N + 1023) / 1024;
    int lo = t * chunk, hi = min(lo + chunk, N);
    int sum = 0;
    for (int i = lo; i < hi; i++) sum += g_cnt[i];
    s[t] = sum;
    __syncthreads();
    for (int off = 1; off < 1024; off <<= 1) {
        int v = (t >= off) ? s[t - off] : 0;
        __syncthreads();
        s[t] += v;
        __syncthreads();
    }
    int run = (t == 0) ? 0 : s[t - 1];
    for (int i = lo; i < hi; i++) {
        g_rowptr[i] = run;
        g_cur[i] = run;
        run += g_cnt[i];
    }
    if (t == 0) g_rowptr[N] = s[1023];
}
__global__ void k_fill(const int* __restrict__ ei, int E) {
    int e = blockIdx.x * blockDim.x + threadIdx.x;
    if (e < E) {
        int d = ei[E + e];
        int p = atomicAdd(&g_cur[d], 1);
        g_csr[p] = ei[e];
    }
}

// ------- CSR aggregate (fp32 sums, tf32 out) + BN-stat zeroing -------------
__global__ void __launch_bounds__(256) k_aggr(int N) {
    if (blockIdx.x == 0 && threadIdx.x < HID) {
        g_sum[threadIdx.x] = 0.f;
        g_sq[threadIdx.x] = 0.f;
    }
    int node = blockIdx.x * 4 + (threadIdx.x >> 6);
    int lane = threadIdx.x & 63;
    if (node >= N) return;
    int s = g_rowptr[node], e = g_rowptr[node + 1];
    float4 acc = make_float4(0.f, 0.f, 0.f, 0.f);
    for (int i = s; i < e; i++) {
        int src = g_csr[i];
        float4 v = *reinterpret_cast<const float4*>(
            g_h + (size_t)src * HID + lane * 4);
        acc.x += v.x; acc.y += v.y; acc.z += v.z; acc.w += v.w;
    }
    uint4 u;
    u.x = f2tf(acc.x); u.y = f2tf(acc.y);
    u.z = f2tf(acc.z); u.w = f2tf(acc.w);
    *reinterpret_cast<uint4*>(g_aggtf + (size_t)node * HID + lane * 4) = u;
}

// ================= tf32 tensor-core GEMM machinery =========================
#define BM 128
#define BN 128
#define BK 32
#define LDS_S 36
#define TS (128 * LDS_S)

__device__ __forceinline__ void mma8(float* c, const unsigned* a,
                                     const unsigned* b) {
    asm volatile(
        "mma.sync.aligned.m16n8k8.row.col.f32.tf32.tf32.f32 "
        "{%0,%1,%2,%3}, {%4,%5,%6,%7}, {%8,%9}, {%0,%1,%2,%3};"
        : "+f"(c[0]), "+f"(c[1]), "+f"(c[2]), "+f"(c[3])
        : "r"(a[0]), "r"(a[1]), "r"(a[2]), "r"(a[3]), "r"(b[0]), "r"(b[1]));
}

// async copy of a 128x32 uint tile (row clamped), 256 threads
__device__ __forceinline__ void async_tile(const unsigned* __restrict__ src,
                                           int row0, int maxrow, int ldk,
                                           int kbase, unsigned* sbuf,
                                           int tid) {
    int r = tid >> 1;
    int gr = min(row0 + r, maxrow - 1);
    const unsigned* p = src + (size_t)gr * ldk + kbase + (tid & 1) * 16;
    unsigned sa = (unsigned)__cvta_generic_to_shared(
        sbuf + r * LDS_S + (tid & 1) * 16);
#pragma unroll
    for (int q = 0; q < 4; q++)
        asm volatile("cp.async.ca.shared.global [%0], [%1], 16;"
                     :: "r"(sa + q * 16), "l"(p + q * 4));
}

// synchronous uint tile load (for edge kernel weights)
__device__ __forceinline__ void load_tile_u(const unsigned* __restrict__ src,
                                            int row0, int maxrow, int ldk,
                                            int kbase, unsigned* s, int tid) {
    int r = tid >> 1;
    int gr = min(row0 + r, maxrow - 1);
    const unsigned* p = src + (size_t)gr * ldk + kbase + (tid & 1) * 16;
    unsigned* d = s + r * LDS_S + (tid & 1) * 16;
#pragma unroll
    for (int q = 0; q < 4; q++)
        *reinterpret_cast<uint4*>(d + q * 4) =
            *reinterpret_cast<const uint4*>(p + q * 4);
}

// one BK=32 stage, 8-warp (2x4) layout, warp tile 64x32
__device__ __forceinline__ void stage_mma(const unsigned* sA,
                                          const unsigned* sB, int wm, int wn,
                                          int lane, float acc[4][4][4]) {
#pragma unroll
    for (int ks = 0; ks < BK / 8; ks++) {
        unsigned a[4][4], b[4][2];
        int col = ks * 8 + (lane & 3);
#pragma unroll
        for (int mt = 0; mt < 4; mt++) {
            int row = wm * 64 + mt * 16 + (lane >> 2);
            const unsigned* p = sA + row * LDS_S + col;
            a[mt][0] = p[0];
            a[mt][1] = p[8 * LDS_S];
            a[mt][2] = p[4];
            a[mt][3] = p[8 * LDS_S + 4];
        }
#pragma unroll
        for (int nt = 0; nt < 4; nt++) {
            int n = wn * 32 + nt * 8 + (lane >> 2);
            const unsigned* p = sB + n * LDS_S + col;
            b[nt][0] = p[0];
            b[nt][1] = p[4];
        }
#pragma unroll
        for (int mt = 0; mt < 4; mt++)
#pragma unroll
            for (int nt = 0; nt < 4; nt++)
                mma8(acc[mt][nt], a[mt], b[nt]);
    }
}

// ---------- node layer: g_out = agg @ Wrel^T + h @ Wroot^T + brel ----------
// cp.async double-buffered; epilogue fuses BN statistics.
__global__ void __launch_bounds__(256, 2)
k_gemm_node(int l, const float* __restrict__ brel, int M) {
    extern __shared__ unsigned dsm[];
    unsigned* sA = dsm;             // 2 buffers of 128*36
    unsigned* sB = dsm + 2 * TS;    // 2 buffers of 128*36

    int tid = threadIdx.x, lane = tid & 31, wid = tid >> 5;
    int wm = wid >> 2, wn = wid & 3;
    int bm = blockIdx.y * BM, bn = blockIdx.x * BN;

    const unsigned* Wr = g_wrel_tf + (size_t)l * HID * HID;
    const unsigned* Wo = g_wroot_tf + (size_t)l * HID * HID;

    float acc[4][4][4] = {};

    // 16 stages: 0-7 = agg@Wrel, 8-15 = h@Wroot
#define PRODUCE(s, buf)                                                     \
    {                                                                       \
        int seg = (s) >> 3, k0 = ((s) & 7) * BK;                            \
        const unsigned* A = seg ? g_htf : g_aggtf;                          \
        const unsigned* W = seg ? Wo : Wr;                                  \
        async_tile(A, bm, M, HID, k0, sA + (buf) * TS, tid);                \
        async_tile(W, bn, HID, HID, k0, sB + (buf) * TS, tid);              \
    }

    PRODUCE(0, 0);
    asm volatile("cp.async.commit_group;");
#pragma unroll 1
    for (int s = 0; s < 16; s++) {
        if (s + 1 < 16) PRODUCE(s + 1, (s + 1) & 1);
        asm volatile("cp.async.commit_group;");
        asm volatile("cp.async.wait_group 1;");
        __syncthreads();
        stage_mma(sA + (s & 1) * TS, sB + (s & 1) * TS, wm, wn, lane, acc);
        __syncthreads();
    }
#undef PRODUCE

    // write + fused BN statistics
#pragma unroll
    for (int nt = 0; nt < 4; nt++) {
        int c = bn + wn * 32 + nt * 8 + 2 * (lane & 3);
        float b0 = brel[c], b1 = brel[c + 1];
        float s0 = 0.f, s1 = 0.f, q0 = 0.f, q1 = 0.f;
#pragma unroll
        for (int mt = 0; mt < 4; mt++) {
            int r0 = bm + wm * 64 + mt * 16 + (lane >> 2);
            if (r0 < M) {
                float v0 = acc[mt][nt][0] + b0;
                float v1 = acc[mt][nt][1] + b1;
                *reinterpret_cast<float2*>(g_out + (size_t)r0 * HID + c) =
                    make_float2(v0, v1);
                s0 += v0; q0 = fmaf(v0, v0, q0);
                s1 += v1; q1 = fmaf(v1, v1, q1);
            }
            if (r0 + 8 < M) {
                float v0 = acc[mt][nt][2] + b0;
                float v1 = acc[mt][nt][3] + b1;
                *reinterpret_cast<float2*>(g_out + (size_t)(r0 + 8) * HID + c) =
                    make_float2(v0, v1);
                s0 += v0; q0 = fmaf(v0, v0, q0);
                s1 += v1; q1 = fmaf(v1, v1, q1);
            }
        }
#pragma unroll
        for (int off = 4; off < 32; off <<= 1) {
            s0 += __shfl_xor_sync(0xffffffffu, s0, off);
            s1 += __shfl_xor_sync(0xffffffffu, s1, off);
            q0 += __shfl_xor_sync(0xffffffffu, q0, off);
            q1 += __shfl_xor_sync(0xffffffffu, q1, off);
        }
        if (lane < 4) {
            atomicAdd(&g_sum[c], s0);
            atomicAdd(&g_sum[c + 1], s1);
            atomicAdd(&g_sq[c], q0);
            atomicAdd(&g_sq[c + 1], q1);
        }
    }
}

// ---------------- BN apply (scale/shift recomputed per block) --------------
__global__ void __launch_bounds__(256) k_bn_apply(const float* __restrict__ gamma,
                                                  const float* __restrict__ beta,
                                                  float invN, int N) {
    int c = threadIdx.x;
    float m = g_sum[c] * invN;
    float var = g_sq[c] * invN - m * m;
    float sc = rsqrtf(var + EPS) * gamma[c];
    float sh = beta[c] - m * sc;
    int r1 = min(blockIdx.x * 8 + 8, N);
    for (int r = blockIdx.x * 8; r < r1; r++) {
        size_t idx = (size_t)r * HID + c;
        float v = fmaf(g_out[idx], sc, sh);
        float hn = g_h[idx] + fmaxf(v, 0.f);
        g_h[idx] = hn;
        g_htf[idx] = f2tf(hn);
    }
}

// ================= fused edge MLP ==========================================
#define ETM 128
#define Z1S 260

__device__ __forceinline__ void stage_mma16(const unsigned* sA, int ldA,
                                            int kA0, const unsigned* sB,
                                            int wm, int wn, int lane,
                                            float acc[2][8][4]) {
#pragma unroll
    for (int ks = 0; ks < 4; ks++) {
        unsigned a[2][4], b[8][2];
        int colA = kA0 + ks * 8 + (lane & 3);
        int colB = ks * 8 + (lane & 3);
#pragma unroll
        for (int mt = 0; mt < 2; mt++) {
            int row = wm * 32 + mt * 16 + (lane >> 2);
            const unsigned* p = sA + row * ldA + colA;
            a[mt][0] = p[0];
            a[mt][1] = p[8 * ldA];
            a[mt][2] = p[4];
            a[mt][3] = p[8 * ldA + 4];
        }
#pragma unroll
        for (int nt = 0; nt < 8; nt++) {
            int n = wn * 64 + nt * 8 + (lane >> 2);
            const unsigned* p = sB + n * LDS_S + colB;
            b[nt][0] = p[0];
            b[nt][1] = p[4];
        }
#pragma unroll
        for (int mt = 0; mt < 2; mt++)
#pragma unroll
            for (int nt = 0; nt < 8; nt++)
                mma8(acc[mt][nt], a[mt], b[nt]);
    }
}

__global__ void __launch_bounds__(512, 1)
k_edge_fused(const int* __restrict__ ei, int E,
             const float* __restrict__ b1, const float* __restrict__ b2,
             const float* __restrict__ W3, const float* __restrict__ b3,
             float* __restrict__ out) {
    extern __shared__ unsigned esm[];
    unsigned* sA = esm;                       // 128*36
    unsigned* sB = sA + ETM * LDS_S;          // 256*36
    unsigned* z1s = sB + 256 * LDS_S;         // 128*260
    float* sdot = (float*)(z1s + ETM * Z1S);  // 128

    int tid = threadIdx.x, lane = tid & 31, wid = tid >> 5;
    int wm = wid >> 2, wn = wid & 3;
    int bm = blockIdx.x * ETM;

    if (tid < ETM) sdot[tid] = 0.f;

    int e = min(bm + (tid >> 2), E - 1);
    int nsrc = ei[e], ndst = ei[E + e];

    float acc[2][8][4] = {};

    // ---- stage 1: z1 = relu(cat(h[src],h[dst]) @ W1^T + b1), K = 512 ------
#pragma unroll 1
    for (int k0 = 0; k0 < 2 * HID; k0 += BK) {
        {
            int kg = k0 + (tid & 3) * 8;
            int node = (kg < HID) ? nsrc : ndst;
            const unsigned* p = g_htf + (size_t)node * HID + (kg & (HID - 1));
            unsigned* d = sA + (tid >> 2) * LDS_S + (tid & 3) * 8;
            *reinterpret_cast<uint4*>(d) = *reinterpret_cast<const uint4*>(p);
            *reinterpret_cast<uint4*>(d + 4) =
                *reinterpret_cast<const uint4*>(p + 4);
        }
        load_tile_u(g_w1tf, 0, HID, 2 * HID, k0, sB, tid);
        __syncthreads();
        stage_mma16(sA, LDS_S, 0, sB, wm, wn, lane, acc);
        __syncthreads();
    }

    // store z1 (bias+relu, tf32) into smem; zero acc for stage 2
#pragma unroll
    for (int mt = 0; mt < 2; mt++) {
        int r0 = wm * 32 + mt * 16 + (lane >> 2);
#pragma unroll
        for (int nt = 0; nt < 8; nt++) {
            int c = wn * 64 + nt * 8 + 2 * (lane & 3);
            float bb0 = b1[c], bb1 = b1[c + 1];
            uint2 u0, u1;
            u0.x = f2tf(fmaxf(acc[mt][nt][0] + bb0, 0.f));
            u0.y = f2tf(fmaxf(acc[mt][nt][1] + bb1, 0.f));
            u1.x = f2tf(fmaxf(acc[mt][nt][2] + bb0, 0.f));
            u1.y = f2tf(fmaxf(acc[mt][nt][3] + bb1, 0.f));
            *reinterpret_cast<uint2*>(z1s + r0 * Z1S + c) = u0;
            *reinterpret_cast<uint2*>(z1s + (r0 + 8) * Z1S + c) = u1;
#pragma unroll
            for (int q = 0; q < 4; q++) acc[mt][nt][q] = 0.f;
        }
    }

    // ---- stage 2: z2 = relu(z1 @ W2^T + b2), K = 256, A from smem ---------
#pragma unroll 1
    for (int k0 = 0; k0 < HID; k0 += BK) {
        load_tile_u(g_w2tf, 0, HID, HID, k0, sB, tid);
        __syncthreads();
        stage_mma16(z1s, Z1S, k0, sB, wm, wn, lane, acc);
        __syncthreads();
    }

    // ---- stage 3: per-edge dot with W3 + sigmoid --------------------------
    float part[2][2] = {};
#pragma unroll
    for (int mt = 0; mt < 2; mt++) {
#pragma unroll
        for (int nt = 0; nt < 8; nt++) {
            int c = wn * 64 + nt * 8 + 2 * (lane & 3);
            float bb0 = b2[c], bb1 = b2[c + 1];
            float w0 = W3[c], w1 = W3[c + 1];
            float z0 = fmaxf(acc[mt][nt][0] + bb0, 0.f);
            float z1v = fmaxf(acc[mt][nt][1] + bb1, 0.f);
            float z2v = fmaxf(acc[mt][nt][2] + bb0, 0.f);
            float z3 = fmaxf(acc[mt][nt][3] + bb1, 0.f);
            part[mt][0] = fmaf(z0, w0, fmaf(z1v, w1, part[mt][0]));
            part[mt][1] = fmaf(z2v, w0, fmaf(z3, w1, part[mt][1]));
        }
    }
#pragma unroll
    for (int off = 1; off < 4; off <<= 1) {
        part[0][0] += __shfl_xor_sync(0xffffffffu, part[0][0], off);
        part[0][1] += __shfl_xor_sync(0xffffffffu, part[0][1], off);
        part[1][0] += __shfl_xor_sync(0xffffffffu, part[1][0], off);
        part[1][1] += __shfl_xor_sync(0xffffffffu, part[1][1], off);
    }
    if ((lane & 3) == 0) {
#pragma unroll
        for (int mt = 0; mt < 2; mt++) {
            int r0 = wm * 32 + mt * 16 + (lane >> 2);
            atomicAdd(&sdot[r0], part[mt][0]);
            atomicAdd(&sdot[r0 + 8], part[mt][1]);
        }
    }
    __syncthreads();
    if (tid < ETM) {
        int eo = bm + tid;
        if (eo < E)
            out[eo] = 1.f / (1.f + expf(-(sdot[tid] + b3[0])));
    }
}

// ---------------- host orchestration ---------------------------------------
extern "C" void kernel_launch(void* const* d_in, const int* in_sizes, int n_in,
                              void* d_out, int out_size) {
    const float* x     = (const float*)d_in[0];
    const int*   ei    = (const int*)d_in[1];
    const float* Win   = (const float*)d_in[2];
    const float* Wrel  = (const float*)d_in[3];
    const float* brel  = (const float*)d_in[4];
    const float* Wroot = (const float*)d_in[5];
    const float* gamma = (const float*)d_in[6];
    const float* beta  = (const float*)d_in[7];
    const float* W1    = (const float*)d_in[8];
    const float* b1    = (const float*)d_in[9];
    const float* W2    = (const float*)d_in[10];
    const float* b2    = (const float*)d_in[11];
    const float* W3    = (const float*)d_in[12];
    const float* b3    = (const float*)d_in[13];

    int N = in_sizes[0] / 2;
    int E = in_sizes[1] / 2;
    float* out = (float*)d_out;

    const size_t gsmem = 4 * (size_t)TS * 4;  // 73728 B
    const size_t esmem =
        (ETM * LDS_S + 256 * LDS_S + (size_t)ETM * Z1S) * 4 + ETM * 4;
    cudaFuncSetAttribute(k_gemm_node,
                         cudaFuncAttributeMaxDynamicSharedMemorySize,
                         (int)gsmem);
    cudaFuncSetAttribute(k_edge_fused,
                         cudaFuncAttributeMaxDynamicSharedMemorySize,
                         (int)esmem);

    // CSR build + weight prep
    k_zero_cnt<<<(N + 255) / 256, 256>>>(N);
    k_hist<<<(E + 255) / 256, 256>>>(ei, E);
    k_scan<<<1, 1024>>>(N);
    k_fill<<<(E + 255) / 256, 256>>>(ei, E);
    k_prep<<<(NLAYERS * HID * HID + 255) / 256, 256>>>(Wrel, Wroot, W1, W2);

    k_input<<<N, HID>>>(x, Win, N);

    dim3 gN(HID / BN, (N + BM - 1) / BM);

    for (int l = 0; l < NLAYERS; l++) {
        k_aggr<<<(N + 3) / 4, 256>>>(N);
        k_gemm_node<<<gN, 256, gsmem>>>(l, brel + (size_t)l * HID, N);
        k_bn_apply<<<(N + 7) / 8, 256>>>(gamma + (size_t)l * HID,
                                         beta + (size_t)l * HID,
                                         1.0f / (float)N, N);
    }

    k_edge_fused<<<(E + ETM - 1) / ETM, 512, esmem>>>(ei, E, b1, b2, W3, b3,
                                                      out);
}

// round 13
// speedup vs baseline: 4.5794x; 1.0231x over previous
#include <cuda_runtime.h>
#include <math.h>
#include <stdint.h>

#define HID 256
#define NLAYERS 15
#define MAXN 50000
#define MAXE 500000
#define EPS 1e-5f

// ---------------- scratch (static device globals) --------------------------
__device__ float g_h[(size_t)MAXN * HID];
__device__ unsigned g_htf[(size_t)MAXN * HID];       // tf32 mirror (root GEMM)
__device__ unsigned short g_hbf[(size_t)MAXN * HID]; // bf16 mirror (gathers)
__device__ unsigned g_aggtf[(size_t)MAXN * HID];     // tf32 aggregation
__device__ float g_out[(size_t)MAXN * HID];
__device__ float g_sum[NLAYERS * HID];
__device__ float g_sq[NLAYERS * HID];
// pre-converted tf32 weights
__device__ unsigned g_wrel_tf[NLAYERS * HID * HID];
__device__ unsigned g_wroot_tf[NLAYERS * HID * HID];
__device__ unsigned g_w1tf[2 * HID * HID];
__device__ unsigned g_w2tf[HID * HID];
// CSR scratch
__device__ int g_cnt[MAXN];
__device__ int g_rowptr[MAXN + 1];
__device__ int g_cur[MAXN];
__device__ int g_csr[MAXE];

__device__ __forceinline__ unsigned f2tf(float f) {
    unsigned u;
    asm("cvt.rna.tf32.f32 %0, %1;" : "=r"(u) : "f"(f));
    return u;
}
// fp32 -> bf16 bits, round-to-nearest-even
__device__ __forceinline__ unsigned short f2bf(float f) {
    unsigned u = __float_as_uint(f);
    u += 0x7fffu + ((u >> 16) & 1u);
    return (unsigned short)(u >> 16);
}

// ---------------- weight prep + stat zeroing -------------------------------
__global__ void k_prep(const float* __restrict__ Wrel,
                       const float* __restrict__ Wroot,
                       const float* __restrict__ W1,
                       const float* __restrict__ W2) {
    int i = blockIdx.x * 256 + threadIdx.x;
    const int NW = NLAYERS * HID * HID;
    if (i < NW) {
        g_wrel_tf[i] = f2tf(Wrel[i]);
        g_wroot_tf[i] = f2tf(Wroot[i]);
    }
    if (i < 2 * HID * HID) g_w1tf[i] = f2tf(W1[i]);
    if (i < HID * HID) g_w2tf[i] = f2tf(W2[i]);
    if (i < NLAYERS * HID) {
        g_sum[i] = 0.f;
        g_sq[i] = 0.f;
    }
}

// ---------------- input fc: h = x @ W_in^T (IN_CH=2) -----------------------
__global__ void k_input(const float* __restrict__ x,
                        const float* __restrict__ Win, int N) {
    int i = blockIdx.x;
    int j = threadIdx.x;
    if (i < N) {
        float v = fmaf(x[2 * i], Win[2 * j], x[2 * i + 1] * Win[2 * j + 1]);
        size_t idx = (size_t)i * HID + j;
        g_h[idx] = v;
        g_htf[idx] = f2tf(v);
        g_hbf[idx] = f2bf(v);
    }
}

// ---------------- CSR build ------------------------------------------------
__global__ void k_zero_cnt(int N) {
    int i = blockIdx.x * blockDim.x + threadIdx.x;
    if (i < N) g_cnt[i] = 0;
}
__global__ void k_hist(const int* __restrict__ ei, int E) {
    int e = blockIdx.x * blockDim.x + threadIdx.x;
    if (e < E) atomicAdd(&g_cnt[ei[E + e]], 1);
}
__global__ void k_scan(int N) {
    __shared__ int s[1024];
    int t = threadIdx.x;
    int chunk = (N + 1023) / 1024;
    int lo = t * chunk, hi = min(lo + chunk, N);
    int sum = 0;
    for (int i = lo; i < hi; i++) sum += g_cnt[i];
    s[t] = sum;
    __syncthreads();
    for (int off = 1; off < 1024; off <<= 1) {
        int v = (t >= off) ? s[t - off] : 0;
        __syncthreads();
        s[t] += v;
        __syncthreads();
    }
    int run = (t == 0) ? 0 : s[t - 1];
    for (int i = lo; i < hi; i++) {
        g_rowptr[i] = run;
        g_cur[i] = run;
        run += g_cnt[i];
    }
    if (t == 0) g_rowptr[N] = s[1023];
}
__global__ void k_fill(const int* __restrict__ ei, int E) {
    int e = blockIdx.x * blockDim.x + threadIdx.x;
    if (e < E) {
        int d = ei[E + e];
        int p = atomicAdd(&g_cur[d], 1);
        g_csr[p] = ei[e];
    }
}

// ------- CSR aggregate: bf16 gather, fp32 accum, tf32 out ------------------
// warp per node: lane covers 8 columns (one LDG.128 of bf16x8 per edge)
__global__ void __launch_bounds__(256) k_aggr(int N) {
    int node = blockIdx.x * 8 + (threadIdx.x >> 5);
    int lane = threadIdx.x & 31;
    if (node >= N) return;
    int s = g_rowptr[node], e = g_rowptr[node + 1];
    float acc[8] = {};
    for (int i = s; i < e; i++) {
        int src = g_csr[i];
        uint4 v = *reinterpret_cast<const uint4*>(
            g_hbf + (size_t)src * HID + lane * 8);
        acc[0] += __uint_as_float(v.x << 16);
        acc[1] += __uint_as_float(v.x & 0xffff0000u);
        acc[2] += __uint_as_float(v.y << 16);
        acc[3] += __uint_as_float(v.y & 0xffff0000u);
        acc[4] += __uint_as_float(v.z << 16);
        acc[5] += __uint_as_float(v.z & 0xffff0000u);
        acc[6] += __uint_as_float(v.w << 16);
        acc[7] += __uint_as_float(v.w & 0xffff0000u);
    }
    unsigned* dst = g_aggtf + (size_t)node * HID + lane * 8;
    uint4 o0, o1;
    o0.x = f2tf(acc[0]); o0.y = f2tf(acc[1]);
    o0.z = f2tf(acc[2]); o0.w = f2tf(acc[3]);
    o1.x = f2tf(acc[4]); o1.y = f2tf(acc[5]);
    o1.z = f2tf(acc[6]); o1.w = f2tf(acc[7]);
    *reinterpret_cast<uint4*>(dst) = o0;
    *reinterpret_cast<uint4*>(dst + 4) = o1;
}

// ================= tf32 tensor-core GEMM machinery =========================
#define BM 128
#define BN 128
#define BK 32
#define LDS_S 36
#define TS (128 * LDS_S)

__device__ __forceinline__ void mma8(float* c, const unsigned* a,
                                     const unsigned* b) {
    asm volatile(
        "mma.sync.aligned.m16n8k8.row.col.f32.tf32.tf32.f32 "
        "{%0,%1,%2,%3}, {%4,%5,%6,%7}, {%8,%9}, {%0,%1,%2,%3};"
        : "+f"(c[0]), "+f"(c[1]), "+f"(c[2]), "+f"(c[3])
        : "r"(a[0]), "r"(a[1]), "r"(a[2]), "r"(a[3]), "r"(b[0]), "r"(b[1]));
}

// async copy of a 128x32 uint tile (row clamped), 256 threads
__device__ __forceinline__ void async_tile(const unsigned* __restrict__ src,
                                           int row0, int maxrow, int ldk,
                                           int kbase, unsigned* sbuf,
                                           int tid) {
    int r = tid >> 1;
    int gr = min(row0 + r, maxrow - 1);
    const unsigned* p = src + (size_t)gr * ldk + kbase + (tid & 1) * 16;
    unsigned sa = (unsigned)__cvta_generic_to_shared(
        sbuf + r * LDS_S + (tid & 1) * 16);
#pragma unroll
    for (int q = 0; q < 4; q++)
        asm volatile("cp.async.ca.shared.global [%0], [%1], 16;"
                     :: "r"(sa + q * 16), "l"(p + q * 4));
}

// synchronous uint tile load (for edge kernel weights)
__device__ __forceinline__ void load_tile_u(const unsigned* __restrict__ src,
                                            int row0, int maxrow, int ldk,
                                            int kbase, unsigned* s, int tid) {
    int r = tid >> 1;
    int gr = min(row0 + r, maxrow - 1);
    const unsigned* p = src + (size_t)gr * ldk + kbase + (tid & 1) * 16;
    unsigned* d = s + r * LDS_S + (tid & 1) * 16;
#pragma unroll
    for (int q = 0; q < 4; q++)
        *reinterpret_cast<uint4*>(d + q * 4) =
            *reinterpret_cast<const uint4*>(p + q * 4);
}

// one BK=32 stage, 8-warp (2x4) layout, warp tile 64x32
__device__ __forceinline__ void stage_mma(const unsigned* sA,
                                          const unsigned* sB, int wm, int wn,
                                          int lane, float acc[4][4][4]) {
#pragma unroll
    for (int ks = 0; ks < BK / 8; ks++) {
        unsigned a[4][4], b[4][2];
        int col = ks * 8 + (lane & 3);
#pragma unroll
        for (int mt = 0; mt < 4; mt++) {
            int row = wm * 64 + mt * 16 + (lane >> 2);
            const unsigned* p = sA + row * LDS_S + col;
            a[mt][0] = p[0];
            a[mt][1] = p[8 * LDS_S];
            a[mt][2] = p[4];
            a[mt][3] = p[8 * LDS_S + 4];
        }
#pragma unroll
        for (int nt = 0; nt < 4; nt++) {
            int n = wn * 32 + nt * 8 + (lane >> 2);
            const unsigned* p = sB + n * LDS_S + col;
            b[nt][0] = p[0];
            b[nt][1] = p[4];
        }
#pragma unroll
        for (int mt = 0; mt < 4; mt++)
#pragma unroll
            for (int nt = 0; nt < 4; nt++)
                mma8(acc[mt][nt], a[mt], b[nt]);
    }
}

// ---------- node layer: g_out = agg @ Wrel^T + h @ Wroot^T + brel ----------
__global__ void __launch_bounds__(256, 2)
k_gemm_node(int l, const float* __restrict__ brel, int M) {
    extern __shared__ unsigned dsm[];
    unsigned* sA = dsm;
    unsigned* sB = dsm + 2 * TS;

    int tid = threadIdx.x, lane = tid & 31, wid = tid >> 5;
    int wm = wid >> 2, wn = wid & 3;
    int bm = blockIdx.y * BM, bn = blockIdx.x * BN;

    const unsigned* Wr = g_wrel_tf + (size_t)l * HID * HID;
    const unsigned* Wo = g_wroot_tf + (size_t)l * HID * HID;

    float acc[4][4][4] = {};

#define PRODUCE(s, buf)                                                     \
    {                                                                       \
        int seg = (s) >> 3, k0 = ((s) & 7) * BK;                            \
        const unsigned* A = seg ? g_htf : g_aggtf;                          \
        const unsigned* W = seg ? Wo : Wr;                                  \
        async_tile(A, bm, M, HID, k0, sA + (buf) * TS, tid);                \
        async_tile(W, bn, HID, HID, k0, sB + (buf) * TS, tid);              \
    }

    PRODUCE(0, 0);
    asm volatile("cp.async.commit_group;");
#pragma unroll 1
    for (int s = 0; s < 16; s++) {
        if (s + 1 < 16) PRODUCE(s + 1, (s + 1) & 1);
        asm volatile("cp.async.commit_group;");
        asm volatile("cp.async.wait_group 1;");
        __syncthreads();
        stage_mma(sA + (s & 1) * TS, sB + (s & 1) * TS, wm, wn, lane, acc);
        __syncthreads();
    }
#undef PRODUCE

    // write + fused BN statistics (per-layer slice)
    float* gsum = g_sum + l * HID;
    float* gsq = g_sq + l * HID;
#pragma unroll
    for (int nt = 0; nt < 4; nt++) {
        int c = bn + wn * 32 + nt * 8 + 2 * (lane & 3);
        float b0 = brel[c], b1 = brel[c + 1];
        float s0 = 0.f, s1 = 0.f, q0 = 0.f, q1 = 0.f;
#pragma unroll
        for (int mt = 0; mt < 4; mt++) {
            int r0 = bm + wm * 64 + mt * 16 + (lane >> 2);
            if (r0 < M) {
                float v0 = acc[mt][nt][0] + b0;
                float v1 = acc[mt][nt][1] + b1;
                *reinterpret_cast<float2*>(g_out + (size_t)r0 * HID + c) =
                    make_float2(v0, v1);
                s0 += v0; q0 = fmaf(v0, v0, q0);
                s1 += v1; q1 = fmaf(v1, v1, q1);
            }
            if (r0 + 8 < M) {
                float v0 = acc[mt][nt][2] + b0;
                float v1 = acc[mt][nt][3] + b1;
                *reinterpret_cast<float2*>(g_out + (size_t)(r0 + 8) * HID + c) =
                    make_float2(v0, v1);
                s0 += v0; q0 = fmaf(v0, v0, q0);
                s1 += v1; q1 = fmaf(v1, v1, q1);
            }
        }
#pragma unroll
        for (int off = 4; off < 32; off <<= 1) {
            s0 += __shfl_xor_sync(0xffffffffu, s0, off);
            s1 += __shfl_xor_sync(0xffffffffu, s1, off);
            q0 += __shfl_xor_sync(0xffffffffu, q0, off);
            q1 += __shfl_xor_sync(0xffffffffu, q1, off);
        }
        if (lane < 4) {
            atomicAdd(&gsum[c], s0);
            atomicAdd(&gsum[c + 1], s1);
            atomicAdd(&gsq[c], q0);
            atomicAdd(&gsq[c + 1], q1);
        }
    }
}

// ---------------- BN apply -------------------------------------------------
__global__ void __launch_bounds__(256) k_bn_apply(const float* __restrict__ gamma,
                                                  const float* __restrict__ beta,
                                                  float invN, int N, int l) {
    int c = threadIdx.x;
    float m = g_sum[l * HID + c] * invN;
    float var = g_sq[l * HID + c] * invN - m * m;
    float sc = rsqrtf(var + EPS) * gamma[c];
    float sh = beta[c] - m * sc;
    int r1 = min(blockIdx.x * 8 + 8, N);
    for (int r = blockIdx.x * 8; r < r1; r++) {
        size_t idx = (size_t)r * HID + c;
        float v = fmaf(g_out[idx], sc, sh);
        float hn = g_h[idx] + fmaxf(v, 0.f);
        g_h[idx] = hn;
        g_htf[idx] = f2tf(hn);
        g_hbf[idx] = f2bf(hn);
    }
}

// ================= fused edge MLP ==========================================
#define ETM 128
#define Z1S 260

__device__ __forceinline__ void stage_mma16(const unsigned* sA, int ldA,
                                            int kA0, const unsigned* sB,
                                            int wm, int wn, int lane,
                                            float acc[2][8][4]) {
#pragma unroll
    for (int ks = 0; ks < 4; ks++) {
        unsigned a[2][4], b[8][2];
        int colA = kA0 + ks * 8 + (lane & 3);
        int colB = ks * 8 + (lane & 3);
#pragma unroll
        for (int mt = 0; mt < 2; mt++) {
            int row = wm * 32 + mt * 16 + (lane >> 2);
            const unsigned* p = sA + row * ldA + colA;
            a[mt][0] = p[0];
            a[mt][1] = p[8 * ldA];
            a[mt][2] = p[4];
            a[mt][3] = p[8 * ldA + 4];
        }
#pragma unroll
        for (int nt = 0; nt < 8; nt++) {
            int n = wn * 64 + nt * 8 + (lane >> 2);
            const unsigned* p = sB + n * LDS_S + colB;
            b[nt][0] = p[0];
            b[nt][1] = p[4];
        }
#pragma unroll
        for (int mt = 0; mt < 2; mt++)
#pragma unroll
            for (int nt = 0; nt < 8; nt++)
                mma8(acc[mt][nt], a[mt], b[nt]);
    }
}

__global__ void __launch_bounds__(512, 1)
k_edge_fused(const int* __restrict__ ei, int E,
             const float* __restrict__ b1, const float* __restrict__ b2,
             const float* __restrict__ W3, const float* __restrict__ b3,
             float* __restrict__ out) {
    extern __shared__ unsigned esm[];
    unsigned* sA = esm;
    unsigned* sB = sA + ETM * LDS_S;
    unsigned* z1s = sB + 256 * LDS_S;
    float* sdot = (float*)(z1s + ETM * Z1S);

    int tid = threadIdx.x, lane = tid & 31, wid = tid >> 5;
    int wm = wid >> 2, wn = wid & 3;
    int bm = blockIdx.x * ETM;

    if (tid < ETM) sdot[tid] = 0.f;

    int e = min(bm + (tid >> 2), E - 1);
    int nsrc = ei[e], ndst = ei[E + e];

    float acc[2][8][4] = {};

    // ---- stage 1: z1 = relu(cat(h[src],h[dst]) @ W1^T + b1), K = 512 ------
#pragma unroll 1
    for (int k0 = 0; k0 < 2 * HID; k0 += BK) {
        {
            int kg = k0 + (tid & 3) * 8;
            int node = (kg < HID) ? nsrc : ndst;
            uint4 v = *reinterpret_cast<const uint4*>(
                g_hbf + (size_t)node * HID + (kg & (HID - 1)));
            unsigned* d = sA + (tid >> 2) * LDS_S + (tid & 3) * 8;
            uint4 lo, hi;
            lo.x = v.x << 16; lo.y = v.x & 0xffff0000u;
            lo.z = v.y << 16; lo.w = v.y & 0xffff0000u;
            hi.x = v.z << 16; hi.y = v.z & 0xffff0000u;
            hi.z = v.w << 16; hi.w = v.w & 0xffff0000u;
            *reinterpret_cast<uint4*>(d) = lo;
            *reinterpret_cast<uint4*>(d + 4) = hi;
        }
        load_tile_u(g_w1tf, 0, HID, 2 * HID, k0, sB, tid);
        __syncthreads();
        stage_mma16(sA, LDS_S, 0, sB, wm, wn, lane, acc);
        __syncthreads();
    }

    // store z1 (bias+relu, tf32) into smem; zero acc for stage 2
#pragma unroll
    for (int mt = 0; mt < 2; mt++) {
        int r0 = wm * 32 + mt * 16 + (lane >> 2);
#pragma unroll
        for (int nt = 0; nt < 8; nt++) {
            int c = wn * 64 + nt * 8 + 2 * (lane & 3);
            float bb0 = b1[c], bb1 = b1[c + 1];
            uint2 u0, u1;
            u0.x = f2tf(fmaxf(acc[mt][nt][0] + bb0, 0.f));
            u0.y = f2tf(fmaxf(acc[mt][nt][1] + bb1, 0.f));
            u1.x = f2tf(fmaxf(acc[mt][nt][2] + bb0, 0.f));
            u1.y = f2tf(fmaxf(acc[mt][nt][3] + bb1, 0.f));
            *reinterpret_cast<uint2*>(z1s + r0 * Z1S + c) = u0;
            *reinterpret_cast<uint2*>(z1s + (r0 + 8) * Z1S + c) = u1;
#pragma unroll
            for (int q = 0; q < 4; q++) acc[mt][nt][q] = 0.f;
        }
    }

    // ---- stage 2: z2 = relu(z1 @ W2^T + b2), K = 256, A from smem ---------
#pragma unroll 1
    for (int k0 = 0; k0 < HID; k0 += BK) {
        load_tile_u(g_w2tf, 0, HID, HID, k0, sB, tid);
        __syncthreads();
        stage_mma16(z1s, Z1S, k0, sB, wm, wn, lane, acc);
        __syncthreads();
    }

    // ---- stage 3: per-edge dot with W3 + sigmoid --------------------------
    float part[2][2] = {};
#pragma unroll
    for (int mt = 0; mt < 2; mt++) {
#pragma unroll
        for (int nt = 0; nt < 8; nt++) {
            int c = wn * 64 + nt * 8 + 2 * (lane & 3);
            float bb0 = b2[c], bb1 = b2[c + 1];
            float w0 = W3[c], w1 = W3[c + 1];
            float z0 = fmaxf(acc[mt][nt][0] + bb0, 0.f);
            float z1v = fmaxf(acc[mt][nt][1] + bb1, 0.f);
            float z2v = fmaxf(acc[mt][nt][2] + bb0, 0.f);
            float z3 = fmaxf(acc[mt][nt][3] + bb1, 0.f);
            part[mt][0] = fmaf(z0, w0, fmaf(z1v, w1, part[mt][0]));
            part[mt][1] = fmaf(z2v, w0, fmaf(z3, w1, part[mt][1]));
        }
    }
#pragma unroll
    for (int off = 1; off < 4; off <<= 1) {
        part[0][0] += __shfl_xor_sync(0xffffffffu, part[0][0], off);
        part[0][1] += __shfl_xor_sync(0xffffffffu, part[0][1], off);
        part[1][0] += __shfl_xor_sync(0xffffffffu, part[1][0], off);
        part[1][1] += __shfl_xor_sync(0xffffffffu, part[1][1], off);
    }
    if ((lane & 3) == 0) {
#pragma unroll
        for (int mt = 0; mt < 2; mt++) {
            int r0 = wm * 32 + mt * 16 + (lane >> 2);
            atomicAdd(&sdot[r0], part[mt][0]);
            atomicAdd(&sdot[r0 + 8], part[mt][1]);
        }
    }
    __syncthreads();
    if (tid < ETM) {
        int eo = bm + tid;
        if (eo < E)
            out[eo] = 1.f / (1.f + expf(-(sdot[tid] + b3[0])));
    }
}

// ---------------- host orchestration ---------------------------------------
extern "C" void kernel_launch(void* const* d_in, const int* in_sizes, int n_in,
                              void* d_out, int out_size) {
    const float* x     = (const float*)d_in[0];
    const int*   ei    = (const int*)d_in[1];
    const float* Win   = (const float*)d_in[2];
    const float* Wrel  = (const float*)d_in[3];
    const float* brel  = (const float*)d_in[4];
    const float* Wroot = (const float*)d_in[5];
    const float* gamma = (const float*)d_in[6];
    const float* beta  = (const float*)d_in[7];
    const float* W1    = (const float*)d_in[8];
    const float* b1    = (const float*)d_in[9];
    const float* W2    = (const float*)d_in[10];
    const float* b2    = (const float*)d_in[11];
    const float* W3    = (const float*)d_in[12];
    const float* b3    = (const float*)d_in[13];

    int N = in_sizes[0] / 2;
    int E = in_sizes[1] / 2;
    float* out = (float*)d_out;

    const size_t gsmem = 4 * (size_t)TS * 4;
    const size_t esmem =
        (ETM * LDS_S + 256 * LDS_S + (size_t)ETM * Z1S) * 4 + ETM * 4;
    cudaFuncSetAttribute(k_gemm_node,
                         cudaFuncAttributeMaxDynamicSharedMemorySize,
                         (int)gsmem);
    cudaFuncSetAttribute(k_edge_fused,
                         cudaFuncAttributeMaxDynamicSharedMemorySize,
                         (int)esmem);

    // CSR build + weight prep + stat zeroing
    k_zero_cnt<<<(N + 255) / 256, 256>>>(N);
    k_hist<<<(E + 255) / 256, 256>>>(ei, E);
    k_scan<<<1, 1024>>>(N);
    k_fill<<<(E + 255) / 256, 256>>>(ei, E);
    k_prep<<<(NLAYERS * HID * HID + 255) / 256, 256>>>(Wrel, Wroot, W1, W2);

    k_input<<<N, HID>>>(x, Win, N);

    dim3 gN(HID / BN, (N + BM - 1) / BM);

    for (int l = 0; l < NLAYERS; l++) {
        k_aggr<<<(N + 7) / 8, 256>>>(N);
        k_gemm_node<<<gN, 256, gsmem>>>(l, brel + (size_t)l * HID, N);
        k_bn_apply<<<(N + 7) / 8, 256>>>(gamma + (size_t)l * HID,
                                         beta + (size_t)l * HID,
                                         1.0f / (float)N, N, l);
    }

    k_edge_fused<<<(E + ETM - 1) / ETM, 512, esmem>>>(ei, E, b1, b2, W3, b3,
                                                      out);
}

// round 14
// speedup vs baseline: 6.8353x; 1.4926x over previous
#include <cuda_runtime.h>
#include <math.h>
#include <stdint.h>

#define HID 256
#define NLAYERS 15
#define MAXN 50000
#define MAXE 500000
#define EPS 1e-5f

typedef unsigned short u16;

// ---------------- scratch (static device globals) --------------------------
__device__ float g_h[(size_t)MAXN * HID];          // fp32 trunk
__device__ u16 g_hbf[(size_t)MAXN * HID];          // bf16 mirror (all GEMM/gather)
__device__ u16 g_aggbf[(size_t)MAXN * HID];        // bf16 aggregation
__device__ float g_out[(size_t)MAXN * HID];
__device__ float g_sum[NLAYERS * HID];
__device__ float g_sq[NLAYERS * HID];
// pre-converted bf16 weights
__device__ u16 g_wrel_bf[NLAYERS * HID * HID];
__device__ u16 g_wroot_bf[NLAYERS * HID * HID];
__device__ u16 g_w1bf[2 * HID * HID];
__device__ u16 g_w2bf[HID * HID];
// CSR scratch
__device__ int g_cnt[MAXN];
__device__ int g_rowptr[MAXN + 1];
__device__ int g_cur[MAXN];
__device__ int g_csr[MAXE];

// fp32 -> bf16 bits, round-to-nearest-even
__device__ __forceinline__ u16 f2bf(float f) {
    unsigned u = __float_as_uint(f);
    u += 0x7fffu + ((u >> 16) & 1u);
    return (u16)(u >> 16);
}
__device__ __forceinline__ unsigned pack2(float lo, float hi) {
    return (unsigned)f2bf(lo) | ((unsigned)f2bf(hi) << 16);
}

// ---------------- weight prep + stat zeroing -------------------------------
__global__ void k_prep(const float* __restrict__ Wrel,
                       const float* __restrict__ Wroot,
                       const float* __restrict__ W1,
                       const float* __restrict__ W2) {
    int i = blockIdx.x * 256 + threadIdx.x;
    const int NW = NLAYERS * HID * HID;
    if (i < NW) {
        g_wrel_bf[i] = f2bf(Wrel[i]);
        g_wroot_bf[i] = f2bf(Wroot[i]);
    }
    if (i < 2 * HID * HID) g_w1bf[i] = f2bf(W1[i]);
    if (i < HID * HID) g_w2bf[i] = f2bf(W2[i]);
    if (i < NLAYERS * HID) {
        g_sum[i] = 0.f;
        g_sq[i] = 0.f;
    }
}

// ---------------- input fc: h = x @ W_in^T (IN_CH=2) -----------------------
__global__ void k_input(const float* __restrict__ x,
                        const float* __restrict__ Win, int N) {
    int i = blockIdx.x;
    int j = threadIdx.x;
    if (i < N) {
        float v = fmaf(x[2 * i], Win[2 * j], x[2 * i + 1] * Win[2 * j + 1]);
        size_t idx = (size_t)i * HID + j;
        g_h[idx] = v;
        g_hbf[idx] = f2bf(v);
    }
}

// ---------------- CSR build ------------------------------------------------
__global__ void k_zero_cnt(int N) {
    int i = blockIdx.x * blockDim.x + threadIdx.x;
    if (i < N) g_cnt[i] = 0;
}
__global__ void k_hist(const int* __restrict__ ei, int E) {
    int e = blockIdx.x * blockDim.x + threadIdx.x;
    if (e < E) atomicAdd(&g_cnt[ei[E + e]], 1);
}
__global__ void k_scan(int N) {
    __shared__ int s[1024];
    int t = threadIdx.x;
    int chunk = (N + 1023) / 1024;
    int lo = t * chunk, hi = min(lo + chunk, N);
    int sum = 0;
    for (int i = lo; i < hi; i++) sum += g_cnt[i];
    s[t] = sum;
    __syncthreads();
    for (int off = 1; off < 1024; off <<= 1) {
        int v = (t >= off) ? s[t - off] : 0;
        __syncthreads();
        s[t] += v;
        __syncthreads();
    }
    int run = (t == 0) ? 0 : s[t - 1];
    for (int i = lo; i < hi; i++) {
        g_rowptr[i] = run;
        g_cur[i] = run;
        run += g_cnt[i];
    }
    if (t == 0) g_rowptr[N] = s[1023];
}
__global__ void k_fill(const int* __restrict__ ei, int E) {
    int e = blockIdx.x * blockDim.x + threadIdx.x;
    if (e < E) {
        int d = ei[E + e];
        int p = atomicAdd(&g_cur[d], 1);
        g_csr[p] = ei[e];
    }
}

// ------- CSR aggregate: bf16 gather, fp32 accum, bf16 out ------------------
__global__ void __launch_bounds__(256) k_aggr(int N) {
    int node = blockIdx.x * 8 + (threadIdx.x >> 5);
    int lane = threadIdx.x & 31;
    if (node >= N) return;
    int s = g_rowptr[node], e = g_rowptr[node + 1];
    float acc[8] = {};
    for (int i = s; i < e; i++) {
        int src = g_csr[i];
        uint4 v = *reinterpret_cast<const uint4*>(
            g_hbf + (size_t)src * HID + lane * 8);
        acc[0] += __uint_as_float(v.x << 16);
        acc[1] += __uint_as_float(v.x & 0xffff0000u);
        acc[2] += __uint_as_float(v.y << 16);
        acc[3] += __uint_as_float(v.y & 0xffff0000u);
        acc[4] += __uint_as_float(v.z << 16);
        acc[5] += __uint_as_float(v.z & 0xffff0000u);
        acc[6] += __uint_as_float(v.w << 16);
        acc[7] += __uint_as_float(v.w & 0xffff0000u);
    }
    uint4 o;
    o.x = pack2(acc[0], acc[1]);
    o.y = pack2(acc[2], acc[3]);
    o.z = pack2(acc[4], acc[5]);
    o.w = pack2(acc[6], acc[7]);
    *reinterpret_cast<uint4*>(g_aggbf + (size_t)node * HID + lane * 8) = o;
}

// ================= bf16 m16n8k16 tensor-core GEMM machinery ================
#define BM 128
#define BN 128
#define BK 32          // bf16 K per stage
#define NSW 20         // smem row stride in 32-bit words (= 40 bf16, pad 8)
#define TSW (128 * NSW)

__device__ __forceinline__ void mma16(float* c, const unsigned* a,
                                      const unsigned* b) {
    asm volatile(
        "mma.sync.aligned.m16n8k16.row.col.f32.bf16.bf16.f32 "
        "{%0,%1,%2,%3}, {%4,%5,%6,%7}, {%8,%9}, {%0,%1,%2,%3};"
        : "+f"(c[0]), "+f"(c[1]), "+f"(c[2]), "+f"(c[3])
        : "r"(a[0]), "r"(a[1]), "r"(a[2]), "r"(a[3]), "r"(b[0]), "r"(b[1]));
}

// cp.async a 128x32 bf16 tile (row clamped): 256 threads, 32B per thread
__device__ __forceinline__ void async_tile(const u16* __restrict__ src,
                                           int row0, int maxrow, int ldk,
                                           int kbase, unsigned* sbuf,
                                           int tid) {
    int r = tid >> 1;
    int gr = min(row0 + r, maxrow - 1);
    const u16* p = src + (size_t)gr * ldk + kbase + (tid & 1) * 16;
    unsigned sa = (unsigned)__cvta_generic_to_shared(
        sbuf + r * NSW + (tid & 1) * 8);
    asm volatile("cp.async.ca.shared.global [%0], [%1], 16;"
                 :: "r"(sa), "l"(p));
    asm volatile("cp.async.ca.shared.global [%0], [%1], 16;"
                 :: "r"(sa + 16), "l"(p + 8));
}

// sync load of a (rows x 32) bf16 tile with 512 threads (2 threads/row)
__device__ __forceinline__ void load_tile_bf(const u16* __restrict__ src,
                                             int ldk, int kbase, unsigned* s,
                                             int tid) {
    int r = tid >> 1;
    const u16* p = src + (size_t)r * ldk + kbase + (tid & 1) * 16;
    unsigned* d = s + r * NSW + (tid & 1) * 8;
    *reinterpret_cast<uint4*>(d) = *reinterpret_cast<const uint4*>(p);
    *reinterpret_cast<uint4*>(d + 4) = *reinterpret_cast<const uint4*>(p + 8);
}

// one BK=32 stage, 8-warp (2x4) layout, warp tile 64x32
__device__ __forceinline__ void stage_mma(const unsigned* sA,
                                          const unsigned* sB, int wm, int wn,
                                          int lane, float acc[4][4][4]) {
#pragma unroll
    for (int ks = 0; ks < 2; ks++) {
        unsigned a[4][4], b[4][2];
        int co = ks * 8 + (lane & 3);
#pragma unroll
        for (int mt = 0; mt < 4; mt++) {
            int row = wm * 64 + mt * 16 + (lane >> 2);
            const unsigned* p = sA + row * NSW + co;
            a[mt][0] = p[0];
            a[mt][1] = p[8 * NSW];
            a[mt][2] = p[4];
            a[mt][3] = p[8 * NSW + 4];
        }
#pragma unroll
        for (int nt = 0; nt < 4; nt++) {
            int n = wn * 32 + nt * 8 + (lane >> 2);
            const unsigned* p = sB + n * NSW + co;
            b[nt][0] = p[0];
            b[nt][1] = p[4];
        }
#pragma unroll
        for (int mt = 0; mt < 4; mt++)
#pragma unroll
            for (int nt = 0; nt < 4; nt++)
                mma16(acc[mt][nt], a[mt], b[nt]);
    }
}

// ---------- node layer: g_out = agg @ Wrel^T + h @ Wroot^T + brel ----------
__global__ void __launch_bounds__(256, 2)
k_gemm_node(int l, const float* __restrict__ brel, int M) {
    extern __shared__ unsigned dsm[];
    unsigned* sA = dsm;               // 2 bufs x 128x20 words
    unsigned* sB = dsm + 2 * TSW;

    int tid = threadIdx.x, lane = tid & 31, wid = tid >> 5;
    int wm = wid >> 2, wn = wid & 3;
    int bm = blockIdx.y * BM, bn = blockIdx.x * BN;

    const u16* Wr = g_wrel_bf + (size_t)l * HID * HID;
    const u16* Wo = g_wroot_bf + (size_t)l * HID * HID;

    float acc[4][4][4] = {};

#define PRODUCE(s, buf)                                                     \
    {                                                                       \
        int seg = (s) >> 3, k0 = ((s) & 7) * BK;                            \
        const u16* A = seg ? g_hbf : g_aggbf;                               \
        const u16* W = seg ? Wo : Wr;                                       \
        async_tile(A, bm, M, HID, k0, sA + (buf) * TSW, tid);               \
        async_tile(W, bn, HID, HID, k0, sB + (buf) * TSW, tid);             \
    }

    PRODUCE(0, 0);
    asm volatile("cp.async.commit_group;");
#pragma unroll 1
    for (int s = 0; s < 16; s++) {
        if (s + 1 < 16) PRODUCE(s + 1, (s + 1) & 1);
        asm volatile("cp.async.commit_group;");
        asm volatile("cp.async.wait_group 1;");
        __syncthreads();
        stage_mma(sA + (s & 1) * TSW, sB + (s & 1) * TSW, wm, wn, lane, acc);
        __syncthreads();
    }
#undef PRODUCE

    // write + fused BN statistics (per-layer slice)
    float* gsum = g_sum + l * HID;
    float* gsq = g_sq + l * HID;
#pragma unroll
    for (int nt = 0; nt < 4; nt++) {
        int c = bn + wn * 32 + nt * 8 + 2 * (lane & 3);
        float b0 = brel[c], b1 = brel[c + 1];
        float s0 = 0.f, s1 = 0.f, q0 = 0.f, q1 = 0.f;
#pragma unroll
        for (int mt = 0; mt < 4; mt++) {
            int r0 = bm + wm * 64 + mt * 16 + (lane >> 2);
            if (r0 < M) {
                float v0 = acc[mt][nt][0] + b0;
                float v1 = acc[mt][nt][1] + b1;
                *reinterpret_cast<float2*>(g_out + (size_t)r0 * HID + c) =
                    make_float2(v0, v1);
                s0 += v0; q0 = fmaf(v0, v0, q0);
                s1 += v1; q1 = fmaf(v1, v1, q1);
            }
            if (r0 + 8 < M) {
                float v0 = acc[mt][nt][2] + b0;
                float v1 = acc[mt][nt][3] + b1;
                *reinterpret_cast<float2*>(g_out + (size_t)(r0 + 8) * HID + c) =
                    make_float2(v0, v1);
                s0 += v0; q0 = fmaf(v0, v0, q0);
                s1 += v1; q1 = fmaf(v1, v1, q1);
            }
        }
#pragma unroll
        for (int off = 4; off < 32; off <<= 1) {
            s0 += __shfl_xor_sync(0xffffffffu, s0, off);
            s1 += __shfl_xor_sync(0xffffffffu, s1, off);
            q0 += __shfl_xor_sync(0xffffffffu, q0, off);
            q1 += __shfl_xor_sync(0xffffffffu, q1, off);
        }
        if (lane < 4) {
            atomicAdd(&gsum[c], s0);
            atomicAdd(&gsum[c + 1], s1);
            atomicAdd(&gsq[c], q0);
            atomicAdd(&gsq[c + 1], q1);
        }
    }
}

// ---------------- BN apply -------------------------------------------------
__global__ void __launch_bounds__(256) k_bn_apply(const float* __restrict__ gamma,
                                                  const float* __restrict__ beta,
                                                  float invN, int N, int l) {
    int c = threadIdx.x;
    float m = g_sum[l * HID + c] * invN;
    float var = g_sq[l * HID + c] * invN - m * m;
    float sc = rsqrtf(var + EPS) * gamma[c];
    float sh = beta[c] - m * sc;
    int r1 = min(blockIdx.x * 8 + 8, N);
    for (int r = blockIdx.x * 8; r < r1; r++) {
        size_t idx = (size_t)r * HID + c;
        float v = fmaf(g_out[idx], sc, sh);
        float hn = g_h[idx] + fmaxf(v, 0.f);
        g_h[idx] = hn;
        g_hbf[idx] = f2bf(hn);
    }
}

// ================= fused edge MLP ==========================================
#define ETM 128
#define Z1W 132   // z1 smem row stride in words (= 264 bf16); 132 mod 8 = 4

// 16-warp (4x4) stage: warp tile 32x64
__device__ __forceinline__ void stage_mma16e(const unsigned* sA, int ldA,
                                             int kw0, const unsigned* sB,
                                             int wm, int wn, int lane,
                                             float acc[2][8][4]) {
#pragma unroll
    for (int ks = 0; ks < 2; ks++) {
        unsigned a[2][4], b[8][2];
        int coA = kw0 + ks * 8 + (lane & 3);
        int coB = ks * 8 + (lane & 3);
#pragma unroll
        for (int mt = 0; mt < 2; mt++) {
            int row = wm * 32 + mt * 16 + (lane >> 2);
            const unsigned* p = sA + row * ldA + coA;
            a[mt][0] = p[0];
            a[mt][1] = p[8 * ldA];
            a[mt][2] = p[4];
            a[mt][3] = p[8 * ldA + 4];
        }
#pragma unroll
        for (int nt = 0; nt < 8; nt++) {
            int n = wn * 64 + nt * 8 + (lane >> 2);
            const unsigned* p = sB + n * NSW + coB;
            b[nt][0] = p[0];
            b[nt][1] = p[4];
        }
#pragma unroll
        for (int mt = 0; mt < 2; mt++)
#pragma unroll
            for (int nt = 0; nt < 8; nt++)
                mma16(acc[mt][nt], a[mt], b[nt]);
    }
}

__global__ void __launch_bounds__(512, 1)
k_edge_fused(const int* __restrict__ ei, int E,
             const float* __restrict__ b1, const float* __restrict__ b2,
             const float* __restrict__ W3, const float* __restrict__ b3,
             float* __restrict__ out) {
    extern __shared__ unsigned esm[];
    unsigned* sA = esm;                        // 128*20 words
    unsigned* sB = sA + ETM * NSW;             // 256*20 words
    unsigned* z1s = sB + 256 * NSW;            // 128*132 words
    float* sdot = (float*)(z1s + ETM * Z1W);   // 128 floats

    int tid = threadIdx.x, lane = tid & 31, wid = tid >> 5;
    int wm = wid >> 2, wn = wid & 3;
    int bm = blockIdx.x * ETM;

    if (tid < ETM) sdot[tid] = 0.f;

    int e = min(bm + (tid >> 2), E - 1);
    int nsrc = ei[e], ndst = ei[E + e];

    float acc[2][8][4] = {};

    // ---- stage 1: z1 = relu(cat(h[src],h[dst]) @ W1^T + b1), K = 512 ------
#pragma unroll 1
    for (int k0 = 0; k0 < 2 * HID; k0 += BK) {
        {
            int kg = k0 + (tid & 3) * 8;
            int node = (kg < HID) ? nsrc : ndst;
            uint4 v = *reinterpret_cast<const uint4*>(
                g_hbf + (size_t)node * HID + (kg & (HID - 1)));
            *reinterpret_cast<uint4*>(sA + (tid >> 2) * NSW + (tid & 3) * 4) = v;
        }
        load_tile_bf(g_w1bf, 2 * HID, k0, sB, tid);
        __syncthreads();
        stage_mma16e(sA, NSW, 0, sB, wm, wn, lane, acc);
        __syncthreads();
    }

    // store z1 (bias+relu, bf16 pairs) into smem; zero acc for stage 2
#pragma unroll
    for (int mt = 0; mt < 2; mt++) {
        int r0 = wm * 32 + mt * 16 + (lane >> 2);
#pragma unroll
        for (int nt = 0; nt < 8; nt++) {
            int c = wn * 64 + nt * 8 + 2 * (lane & 3);
            float bb0 = b1[c], bb1 = b1[c + 1];
            z1s[r0 * Z1W + (c >> 1)] =
                pack2(fmaxf(acc[mt][nt][0] + bb0, 0.f),
                      fmaxf(acc[mt][nt][1] + bb1, 0.f));
            z1s[(r0 + 8) * Z1W + (c >> 1)] =
                pack2(fmaxf(acc[mt][nt][2] + bb0, 0.f),
                      fmaxf(acc[mt][nt][3] + bb1, 0.f));
#pragma unroll
            for (int q = 0; q < 4; q++) acc[mt][nt][q] = 0.f;
        }
    }

    // ---- stage 2: z2 = relu(z1 @ W2^T + b2), K = 256, A from smem ---------
#pragma unroll 1
    for (int k0 = 0; k0 < HID; k0 += BK) {
        load_tile_bf(g_w2bf, HID, k0, sB, tid);
        __syncthreads();
        stage_mma16e(z1s, Z1W, k0 >> 1, sB, wm, wn, lane, acc);
        __syncthreads();
    }

    // ---- stage 3: per-edge dot with W3 + sigmoid --------------------------
    float part[2][2] = {};
#pragma unroll
    for (int mt = 0; mt < 2; mt++) {
#pragma unroll
        for (int nt = 0; nt < 8; nt++) {
            int c = wn * 64 + nt * 8 + 2 * (lane & 3);
            float bb0 = b2[c], bb1 = b2[c + 1];
            float w0 = W3[c], w1 = W3[c + 1];
            float z0 = fmaxf(acc[mt][nt][0] + bb0, 0.f);
            float z1v = fmaxf(acc[mt][nt][1] + bb1, 0.f);
            float z2v = fmaxf(acc[mt][nt][2] + bb0, 0.f);
            float z3 = fmaxf(acc[mt][nt][3] + bb1, 0.f);
            part[mt][0] = fmaf(z0, w0, fmaf(z1v, w1, part[mt][0]));
            part[mt][1] = fmaf(z2v, w0, fmaf(z3, w1, part[mt][1]));
        }
    }
#pragma unroll
    for (int off = 1; off < 4; off <<= 1) {
        part[0][0] += __shfl_xor_sync(0xffffffffu, part[0][0], off);
        part[0][1] += __shfl_xor_sync(0xffffffffu, part[0][1], off);
        part[1][0] += __shfl_xor_sync(0xffffffffu, part[1][0], off);
        part[1][1] += __shfl_xor_sync(0xffffffffu, part[1][1], off);
    }
    if ((lane & 3) == 0) {
#pragma unroll
        for (int mt = 0; mt < 2; mt++) {
            int r0 = wm * 32 + mt * 16 + (lane >> 2);
            atomicAdd(&sdot[r0], part[mt][0]);
            atomicAdd(&sdot[r0 + 8], part[mt][1]);
        }
    }
    __syncthreads();
    if (tid < ETM) {
        int eo = bm + tid;
        if (eo < E)
            out[eo] = 1.f / (1.f + expf(-(sdot[tid] + b3[0])));
    }
}

// ---------------- host orchestration ---------------------------------------
extern "C" void kernel_launch(void* const* d_in, const int* in_sizes, int n_in,
                              void* d_out, int out_size) {
    const float* x     = (const float*)d_in[0];
    const int*   ei    = (const int*)d_in[1];
    const float* Win   = (const float*)d_in[2];
    const float* Wrel  = (const float*)d_in[3];
    const float* brel  = (const float*)d_in[4];
    const float* Wroot = (const float*)d_in[5];
    const float* gamma = (const float*)d_in[6];
    const float* beta  = (const float*)d_in[7];
    const float* W1    = (const float*)d_in[8];
    const float* b1    = (const float*)d_in[9];
    const float* W2    = (const float*)d_in[10];
    const float* b2    = (const float*)d_in[11];
    const float* W3    = (const float*)d_in[12];
    const float* b3    = (const float*)d_in[13];

    int N = in_sizes[0] / 2;
    int E = in_sizes[1] / 2;
    float* out = (float*)d_out;

    const size_t gsmem = 4 * (size_t)TSW * 4;                 // 40960 B
    const size_t esmem =
        (ETM * NSW + 256 * NSW + (size_t)ETM * Z1W) * 4 + ETM * 4;  // 98816 B
    cudaFuncSetAttribute(k_gemm_node,
                         cudaFuncAttributeMaxDynamicSharedMemorySize,
                         (int)gsmem);
    cudaFuncSetAttribute(k_edge_fused,
                         cudaFuncAttributeMaxDynamicSharedMemorySize,
                         (int)esmem);

    // CSR build + weight prep + stat zeroing
    k_zero_cnt<<<(N + 255) / 256, 256>>>(N);
    k_hist<<<(E + 255) / 256, 256>>>(ei, E);
    k_scan<<<1, 1024>>>(N);
    k_fill<<<(E + 255) / 256, 256>>>(ei, E);
    k_prep<<<(NLAYERS * HID * HID + 255) / 256, 256>>>(Wrel, Wroot, W1, W2);

    k_input<<<N, HID>>>(x, Win, N);

    dim3 gN(HID / BN, (N + BM - 1) / BM);

    for (int l = 0; l < NLAYERS; l++) {
        k_aggr<<<(N + 7) / 8, 256>>>(N);
        k_gemm_node<<<gN, 256, gsmem>>>(l, brel + (size_t)l * HID, N);
        k_bn_apply<<<(N + 7) / 8, 256>>>(gamma + (size_t)l * HID,
                                         beta + (size_t)l * HID,
                                         1.0f / (float)N, N, l);
    }

    k_edge_fused<<<(E + ETM - 1) / ETM, 512, esmem>>>(ei, E, b1, b2, W3, b3,
                                                      out);
}

// round 15
// speedup vs baseline: 7.5229x; 1.1006x over previous
#include <cuda_runtime.h>
#include <math.h>
#include <stdint.h>

#define HID 256
#define NLAYERS 15
#define MAXN 50000
#define MAXE 500000
#define EPS 1e-5f

typedef unsigned short u16;

// ---------------- scratch (static device globals) --------------------------
__device__ float g_h[(size_t)MAXN * HID];          // fp32 trunk
__device__ u16 g_hbf[(size_t)MAXN * HID];          // bf16 mirror (GEMM/gather)
__device__ u16 g_aggbf[(size_t)MAXN * HID];        // bf16 aggregation
__device__ unsigned g_outp[(size_t)MAXN * HID / 2]; // bf16 pair layer output
__device__ float g_sum[NLAYERS * HID];
__device__ float g_sq[NLAYERS * HID];
// pre-converted bf16 weights
__device__ u16 g_wrel_bf[NLAYERS * HID * HID];
__device__ u16 g_wroot_bf[NLAYERS * HID * HID];
__device__ u16 g_w1bf[2 * HID * HID];
__device__ u16 g_w2bf[HID * HID];
// CSR scratch
__device__ int g_cnt[MAXN];
__device__ int g_rowptr[MAXN + 1];
__device__ int g_cur[MAXN];
__device__ int g_csr[MAXE];

// fp32 -> bf16 bits, round-to-nearest-even
__device__ __forceinline__ u16 f2bf(float f) {
    unsigned u = __float_as_uint(f);
    u += 0x7fffu + ((u >> 16) & 1u);
    return (u16)(u >> 16);
}
__device__ __forceinline__ unsigned pack2(float lo, float hi) {
    return (unsigned)f2bf(lo) | ((unsigned)f2bf(hi) << 16);
}
__device__ __forceinline__ float bflo(unsigned p) {
    return __uint_as_float(p << 16);
}
__device__ __forceinline__ float bfhi(unsigned p) {
    return __uint_as_float(p & 0xffff0000u);
}

// ---------------- weight prep + stat zeroing -------------------------------
__global__ void k_prep(const float* __restrict__ Wrel,
                       const float* __restrict__ Wroot,
                       const float* __restrict__ W1,
                       const float* __restrict__ W2) {
    int i = blockIdx.x * 256 + threadIdx.x;
    const int NW = NLAYERS * HID * HID;
    if (i < NW) {
        g_wrel_bf[i] = f2bf(Wrel[i]);
        g_wroot_bf[i] = f2bf(Wroot[i]);
    }
    if (i < 2 * HID * HID) g_w1bf[i] = f2bf(W1[i]);
    if (i < HID * HID) g_w2bf[i] = f2bf(W2[i]);
    if (i < NLAYERS * HID) {
        g_sum[i] = 0.f;
        g_sq[i] = 0.f;
    }
}

// ---------------- input fc: h = x @ W_in^T (IN_CH=2) -----------------------
__global__ void k_input(const float* __restrict__ x,
                        const float* __restrict__ Win, int N) {
    int i = blockIdx.x;
    int j = threadIdx.x;
    if (i < N) {
        float v = fmaf(x[2 * i], Win[2 * j], x[2 * i + 1] * Win[2 * j + 1]);
        size_t idx = (size_t)i * HID + j;
        g_h[idx] = v;
        g_hbf[idx] = f2bf(v);
    }
}

// ---------------- CSR build ------------------------------------------------
__global__ void k_zero_cnt(int N) {
    int i = blockIdx.x * blockDim.x + threadIdx.x;
    if (i < N) g_cnt[i] = 0;
}
__global__ void k_hist(const int* __restrict__ ei, int E) {
    int e = blockIdx.x * blockDim.x + threadIdx.x;
    if (e < E) atomicAdd(&g_cnt[ei[E + e]], 1);
}
__global__ void k_scan(int N) {
    __shared__ int s[1024];
    int t = threadIdx.x;
    int chunk = (N + 1023) / 1024;
    int lo = t * chunk, hi = min(lo + chunk, N);
    int sum = 0;
    for (int i = lo; i < hi; i++) sum += g_cnt[i];
    s[t] = sum;
    __syncthreads();
    for (int off = 1; off < 1024; off <<= 1) {
        int v = (t >= off) ? s[t - off] : 0;
        __syncthreads();
        s[t] += v;
        __syncthreads();
    }
    int run = (t == 0) ? 0 : s[t - 1];
    for (int i = lo; i < hi; i++) {
        g_rowptr[i] = run;
        g_cur[i] = run;
        run += g_cnt[i];
    }
    if (t == 0) g_rowptr[N] = s[1023];
}
__global__ void k_fill(const int* __restrict__ ei, int E) {
    int e = blockIdx.x * blockDim.x + threadIdx.x;
    if (e < E) {
        int d = ei[E + e];
        int p = atomicAdd(&g_cur[d], 1);
        g_csr[p] = ei[e];
    }
}

// ------- CSR aggregate: bf16 gather, fp32 accum, bf16 out ------------------
__global__ void __launch_bounds__(256) k_aggr(int N) {
    int node = blockIdx.x * 8 + (threadIdx.x >> 5);
    int lane = threadIdx.x & 31;
    if (node >= N) return;
    int s = g_rowptr[node], e = g_rowptr[node + 1];
    float acc[8] = {};
    for (int i = s; i < e; i++) {
        int src = g_csr[i];
        uint4 v = *reinterpret_cast<const uint4*>(
            g_hbf + (size_t)src * HID + lane * 8);
        acc[0] += bflo(v.x); acc[1] += bfhi(v.x);
        acc[2] += bflo(v.y); acc[3] += bfhi(v.y);
        acc[4] += bflo(v.z); acc[5] += bfhi(v.z);
        acc[6] += bflo(v.w); acc[7] += bfhi(v.w);
    }
    uint4 o;
    o.x = pack2(acc[0], acc[1]);
    o.y = pack2(acc[2], acc[3]);
    o.z = pack2(acc[4], acc[5]);
    o.w = pack2(acc[6], acc[7]);
    *reinterpret_cast<uint4*>(g_aggbf + (size_t)node * HID + lane * 8) = o;
}

// ================= bf16 m16n8k16 tensor-core GEMM machinery ================
#define BM 128
#define BN 128
#define BK 32          // bf16 K per stage
#define NSW 20         // smem row stride in 32-bit words (= 40 bf16, pad 8)
#define TSW (128 * NSW)

__device__ __forceinline__ void mma16(float* c, const unsigned* a,
                                      const unsigned* b) {
    asm volatile(
        "mma.sync.aligned.m16n8k16.row.col.f32.bf16.bf16.f32 "
        "{%0,%1,%2,%3}, {%4,%5,%6,%7}, {%8,%9}, {%0,%1,%2,%3};"
        : "+f"(c[0]), "+f"(c[1]), "+f"(c[2]), "+f"(c[3])
        : "r"(a[0]), "r"(a[1]), "r"(a[2]), "r"(a[3]), "r"(b[0]), "r"(b[1]));
}

// cp.async a 128x32 bf16 tile (row clamped): 256 threads, 32B per thread
__device__ __forceinline__ void async_tile(const u16* __restrict__ src,
                                           int row0, int maxrow, int ldk,
                                           int kbase, unsigned* sbuf,
                                           int tid) {
    int r = tid >> 1;
    int gr = min(row0 + r, maxrow - 1);
    const u16* p = src + (size_t)gr * ldk + kbase + (tid & 1) * 16;
    unsigned sa = (unsigned)__cvta_generic_to_shared(
        sbuf + r * NSW + (tid & 1) * 8);
    asm volatile("cp.async.ca.shared.global [%0], [%1], 16;"
                 :: "r"(sa), "l"(p));
    asm volatile("cp.async.ca.shared.global [%0], [%1], 16;"
                 :: "r"(sa + 16), "l"(p + 8));
}

// cp.async a (256 x 32) bf16 tile with 512 threads (2 threads/row)
__device__ __forceinline__ void async_tile512(const u16* __restrict__ src,
                                              int ldk, int kbase,
                                              unsigned* sbuf, int tid) {
    int r = tid >> 1;
    const u16* p = src + (size_t)r * ldk + kbase + (tid & 1) * 16;
    unsigned sa = (unsigned)__cvta_generic_to_shared(
        sbuf + r * NSW + (tid & 1) * 8);
    asm volatile("cp.async.ca.shared.global [%0], [%1], 16;"
                 :: "r"(sa), "l"(p));
    asm volatile("cp.async.ca.shared.global [%0], [%1], 16;"
                 :: "r"(sa + 16), "l"(p + 8));
}

// one BK=32 stage, 8-warp (2x4) layout, warp tile 64x32
__device__ __forceinline__ void stage_mma(const unsigned* sA,
                                          const unsigned* sB, int wm, int wn,
                                          int lane, float acc[4][4][4]) {
#pragma unroll
    for (int ks = 0; ks < 2; ks++) {
        unsigned a[4][4], b[4][2];
        int co = ks * 8 + (lane & 3);
#pragma unroll
        for (int mt = 0; mt < 4; mt++) {
            int row = wm * 64 + mt * 16 + (lane >> 2);
            const unsigned* p = sA + row * NSW + co;
            a[mt][0] = p[0];
            a[mt][1] = p[8 * NSW];
            a[mt][2] = p[4];
            a[mt][3] = p[8 * NSW + 4];
        }
#pragma unroll
        for (int nt = 0; nt < 4; nt++) {
            int n = wn * 32 + nt * 8 + (lane >> 2);
            const unsigned* p = sB + n * NSW + co;
            b[nt][0] = p[0];
            b[nt][1] = p[4];
        }
#pragma unroll
        for (int mt = 0; mt < 4; mt++)
#pragma unroll
            for (int nt = 0; nt < 4; nt++)
                mma16(acc[mt][nt], a[mt], b[nt]);
    }
}

// ---------- node layer: g_out = agg @ Wrel^T + h @ Wroot^T + brel ----------
// 3-stage cp.async ring, ONE barrier per K-stage; epilogue fuses BN stats and
// writes g_out as bf16 pairs (stats from fp32 pre-rounding values).
__global__ void __launch_bounds__(256, 2)
k_gemm_node(int l, const float* __restrict__ brel, int M) {
    extern __shared__ unsigned dsm[];
    unsigned* sA = dsm;               // 3 bufs x 128x20 words
    unsigned* sB = dsm + 3 * TSW;     // 3 bufs x 128x20 words

    int tid = threadIdx.x, lane = tid & 31, wid = tid >> 5;
    int wm = wid >> 2, wn = wid & 3;
    int bm = blockIdx.y * BM, bn = blockIdx.x * BN;

    const u16* Wr = g_wrel_bf + (size_t)l * HID * HID;
    const u16* Wo = g_wroot_bf + (size_t)l * HID * HID;

    float acc[4][4][4] = {};

#define PRODUCE(s, buf)                                                     \
    {                                                                       \
        int seg = (s) >> 3, k0 = ((s) & 7) * BK;                            \
        const u16* A = seg ? g_hbf : g_aggbf;                               \
        const u16* W = seg ? Wo : Wr;                                       \
        async_tile(A, bm, M, HID, k0, sA + (buf) * TSW, tid);               \
        async_tile(W, bn, HID, HID, k0, sB + (buf) * TSW, tid);             \
    }

    PRODUCE(0, 0);
    asm volatile("cp.async.commit_group;");
    PRODUCE(1, 1);
    asm volatile("cp.async.commit_group;");
#pragma unroll 1
    for (int s = 0; s < 16; s++) {
        asm volatile("cp.async.wait_group 1;");
        __syncthreads();
        int cur = s - (s / 3) * 3;           // s % 3
        stage_mma(sA + cur * TSW, sB + cur * TSW, wm, wn, lane, acc);
        if (s + 2 < 16) {
            int nxt = (s + 2) - ((s + 2) / 3) * 3;
            PRODUCE(s + 2, nxt);
        }
        asm volatile("cp.async.commit_group;");
    }
#undef PRODUCE

    // write (bf16 pairs) + fused BN statistics (fp32, pre-rounding)
    float* gsum = g_sum + l * HID;
    float* gsq = g_sq + l * HID;
#pragma unroll
    for (int nt = 0; nt < 4; nt++) {
        int c = bn + wn * 32 + nt * 8 + 2 * (lane & 3);
        float b0 = brel[c], b1 = brel[c + 1];
        float s0 = 0.f, s1 = 0.f, q0 = 0.f, q1 = 0.f;
#pragma unroll
        for (int mt = 0; mt < 4; mt++) {
            int r0 = bm + wm * 64 + mt * 16 + (lane >> 2);
            if (r0 < M) {
                float v0 = acc[mt][nt][0] + b0;
                float v1 = acc[mt][nt][1] + b1;
                g_outp[(size_t)r0 * (HID / 2) + (c >> 1)] = pack2(v0, v1);
                s0 += v0; q0 = fmaf(v0, v0, q0);
                s1 += v1; q1 = fmaf(v1, v1, q1);
            }
            if (r0 + 8 < M) {
                float v0 = acc[mt][nt][2] + b0;
                float v1 = acc[mt][nt][3] + b1;
                g_outp[(size_t)(r0 + 8) * (HID / 2) + (c >> 1)] = pack2(v0, v1);
                s0 += v0; q0 = fmaf(v0, v0, q0);
                s1 += v1; q1 = fmaf(v1, v1, q1);
            }
        }
#pragma unroll
        for (int off = 4; off < 32; off <<= 1) {
            s0 += __shfl_xor_sync(0xffffffffu, s0, off);
            s1 += __shfl_xor_sync(0xffffffffu, s1, off);
            q0 += __shfl_xor_sync(0xffffffffu, q0, off);
            q1 += __shfl_xor_sync(0xffffffffu, q1, off);
        }
        if (lane < 4) {
            atomicAdd(&gsum[c], s0);
            atomicAdd(&gsum[c + 1], s1);
            atomicAdd(&gsq[c], q0);
            atomicAdd(&gsq[c + 1], q1);
        }
    }
}

// ---------------- BN apply (bf16 g_out pairs, 16 rows/block) ---------------
__global__ void __launch_bounds__(256) k_bn_apply(const float* __restrict__ gamma,
                                                  const float* __restrict__ beta,
                                                  float invN, int N, int l) {
    int tid = threadIdx.x;
    int cp = tid & 127;       // column pair index
    int half = tid >> 7;      // 0 or 1
    int c = cp * 2;
    float m0 = g_sum[l * HID + c] * invN;
    float m1 = g_sum[l * HID + c + 1] * invN;
    float v0 = g_sq[l * HID + c] * invN - m0 * m0;
    float v1 = g_sq[l * HID + c + 1] * invN - m1 * m1;
    float sc0 = rsqrtf(v0 + EPS) * gamma[c];
    float sc1 = rsqrtf(v1 + EPS) * gamma[c + 1];
    float sh0 = beta[c] - m0 * sc0;
    float sh1 = beta[c + 1] - m1 * sc1;

    unsigned* hbfp = reinterpret_cast<unsigned*>(g_hbf);
    int r0 = blockIdx.x * 16 + half * 8;
    int r1 = min(r0 + 8, N);
    for (int r = r0; r < r1; r++) {
        unsigned p = g_outp[(size_t)r * 128 + cp];
        float o0 = fmaf(bflo(p), sc0, sh0);
        float o1 = fmaf(bfhi(p), sc1, sh1);
        float2 h = *reinterpret_cast<float2*>(g_h + (size_t)r * HID + c);
        h.x += fmaxf(o0, 0.f);
        h.y += fmaxf(o1, 0.f);
        *reinterpret_cast<float2*>(g_h + (size_t)r * HID + c) = h;
        hbfp[(size_t)r * 128 + cp] = pack2(h.x, h.y);
    }
}

// ================= fused edge MLP ==========================================
#define ETM 128
#define Z1W 132   // z1 smem row stride in words (= 264 bf16); conflict-free

// 16-warp (4x4) stage: warp tile 32x64
__device__ __forceinline__ void stage_mma16e(const unsigned* sA, int ldA,
                                             int kw0, const unsigned* sB,
                                             int wm, int wn, int lane,
                                             float acc[2][8][4]) {
#pragma unroll
    for (int ks = 0; ks < 2; ks++) {
        unsigned a[2][4], b[8][2];
        int coA = kw0 + ks * 8 + (lane & 3);
        int coB = ks * 8 + (lane & 3);
#pragma unroll
        for (int mt = 0; mt < 2; mt++) {
            int row = wm * 32 + mt * 16 + (lane >> 2);
            const unsigned* p = sA + row * ldA + coA;
            a[mt][0] = p[0];
            a[mt][1] = p[8 * ldA];
            a[mt][2] = p[4];
            a[mt][3] = p[8 * ldA + 4];
        }
#pragma unroll
        for (int nt = 0; nt < 8; nt++) {
            int n = wn * 64 + nt * 8 + (lane >> 2);
            const unsigned* p = sB + n * NSW + coB;
            b[nt][0] = p[0];
            b[nt][1] = p[4];
        }
#pragma unroll
        for (int mt = 0; mt < 2; mt++)
#pragma unroll
            for (int nt = 0; nt < 8; nt++)
                mma16(acc[mt][nt], a[mt], b[nt]);
    }
}

__global__ void __launch_bounds__(512, 1)
k_edge_fused(const int* __restrict__ ei, int E,
             const float* __restrict__ b1, const float* __restrict__ b2,
             const float* __restrict__ W3, const float* __restrict__ b3,
             float* __restrict__ out) {
    extern __shared__ unsigned esm[];
    unsigned* sA = esm;                        // 128*20 words
    unsigned* sB = sA + ETM * NSW;             // 256*20 words
    unsigned* z1s = sB + 256 * NSW;            // 128*132 words
    float* sdot = (float*)(z1s + ETM * Z1W);   // 128 floats

    int tid = threadIdx.x, lane = tid & 31, wid = tid >> 5;
    int wm = wid >> 2, wn = wid & 3;
    int bm = blockIdx.x * ETM;

    if (tid < ETM) sdot[tid] = 0.f;

    int e = min(bm + (tid >> 2), E - 1);
    int nsrc = ei[e], ndst = ei[E + e];

    float acc[2][8][4] = {};

    // ---- stage 1: z1 = relu(cat(h[src],h[dst]) @ W1^T + b1), K = 512 ------
#pragma unroll 1
    for (int k0 = 0; k0 < 2 * HID; k0 += BK) {
        {
            // gather: cp.async 16B per thread from h rows
            int kg = k0 + (tid & 3) * 8;
            int node = (kg < HID) ? nsrc : ndst;
            const u16* p = g_hbf + (size_t)node * HID + (kg & (HID - 1));
            unsigned sa = (unsigned)__cvta_generic_to_shared(
                sA + (tid >> 2) * NSW + (tid & 3) * 4);
            asm volatile("cp.async.ca.shared.global [%0], [%1], 16;"
                         :: "r"(sa), "l"(p));
        }
        async_tile512(g_w1bf, 2 * HID, k0, sB, tid);
        asm volatile("cp.async.commit_group;");
        asm volatile("cp.async.wait_group 0;");
        __syncthreads();
        stage_mma16e(sA, NSW, 0, sB, wm, wn, lane, acc);
        __syncthreads();
    }

    // store z1 (bias+relu, bf16 pairs) into smem; zero acc for stage 2
#pragma unroll
    for (int mt = 0; mt < 2; mt++) {
        int r0 = wm * 32 + mt * 16 + (lane >> 2);
#pragma unroll
        for (int nt = 0; nt < 8; nt++) {
            int c = wn * 64 + nt * 8 + 2 * (lane & 3);
            float bb0 = b1[c], bb1 = b1[c + 1];
            z1s[r0 * Z1W + (c >> 1)] =
                pack2(fmaxf(acc[mt][nt][0] + bb0, 0.f),
                      fmaxf(acc[mt][nt][1] + bb1, 0.f));
            z1s[(r0 + 8) * Z1W + (c >> 1)] =
                pack2(fmaxf(acc[mt][nt][2] + bb0, 0.f),
                      fmaxf(acc[mt][nt][3] + bb1, 0.f));
#pragma unroll
            for (int q = 0; q < 4; q++) acc[mt][nt][q] = 0.f;
        }
    }

    // ---- stage 2: z2 = relu(z1 @ W2^T + b2), K = 256, A from smem ---------
#pragma unroll 1
    for (int k0 = 0; k0 < HID; k0 += BK) {
        async_tile512(g_w2bf, HID, k0, sB, tid);
        asm volatile("cp.async.commit_group;");
        asm volatile("cp.async.wait_group 0;");
        __syncthreads();
        stage_mma16e(z1s, Z1W, k0 >> 1, sB, wm, wn, lane, acc);
        __syncthreads();
    }

    // ---- stage 3: per-edge dot with W3 + sigmoid --------------------------
    float part[2][2] = {};
#pragma unroll
    for (int mt = 0; mt < 2; mt++) {
#pragma unroll
        for (int nt = 0; nt < 8; nt++) {
            int c = wn * 64 + nt * 8 + 2 * (lane & 3);
            float bb0 = b2[c], bb1 = b2[c + 1];
            float w0 = W3[c], w1 = W3[c + 1];
            float z0 = fmaxf(acc[mt][nt][0] + bb0, 0.f);
            float z1v = fmaxf(acc[mt][nt][1] + bb1, 0.f);
            float z2v = fmaxf(acc[mt][nt][2] + bb0, 0.f);
            float z3 = fmaxf(acc[mt][nt][3] + bb1, 0.f);
            part[mt][0] = fmaf(z0, w0, fmaf(z1v, w1, part[mt][0]));
            part[mt][1] = fmaf(z2v, w0, fmaf(z3, w1, part[mt][1]));
        }
    }
#pragma unroll
    for (int off = 1; off < 4; off <<= 1) {
        part[0][0] += __shfl_xor_sync(0xffffffffu, part[0][0], off);
        part[0][1] += __shfl_xor_sync(0xffffffffu, part[0][1], off);
        part[1][0] += __shfl_xor_sync(0xffffffffu, part[1][0], off);
        part[1][1] += __shfl_xor_sync(0xffffffffu, part[1][1], off);
    }
    if ((lane & 3) == 0) {
#pragma unroll
        for (int mt = 0; mt < 2; mt++) {
            int r0 = wm * 32 + mt * 16 + (lane >> 2);
            atomicAdd(&sdot[r0], part[mt][0]);
            atomicAdd(&sdot[r0 + 8], part[mt][1]);
        }
    }
    __syncthreads();
    if (tid < ETM) {
        int eo = bm + tid;
        if (eo < E)
            out[eo] = 1.f / (1.f + expf(-(sdot[tid] + b3[0])));
    }
}

// ---------------- host orchestration ---------------------------------------
extern "C" void kernel_launch(void* const* d_in, const int* in_sizes, int n_in,
                              void* d_out, int out_size) {
    const float* x     = (const float*)d_in[0];
    const int*   ei    = (const int*)d_in[1];
    const float* Win   = (const float*)d_in[2];
    const float* Wrel  = (const float*)d_in[3];
    const float* brel  = (const float*)d_in[4];
    const float* Wroot = (const float*)d_in[5];
    const float* gamma = (const float*)d_in[6];
    const float* beta  = (const float*)d_in[7];
    const float* W1    = (const float*)d_in[8];
    const float* b1    = (const float*)d_in[9];
    const float* W2    = (const float*)d_in[10];
    const float* b2    = (const float*)d_in[11];
    const float* W3    = (const float*)d_in[12];
    const float* b3    = (const float*)d_in[13];

    int N = in_sizes[0] / 2;
    int E = in_sizes[1] / 2;
    float* out = (float*)d_out;

    const size_t gsmem = 6 * (size_t)TSW * 4;                 // 61440 B
    const size_t esmem =
        (ETM * NSW + 256 * NSW + (size_t)ETM * Z1W) * 4 + ETM * 4;  // 98816 B
    cudaFuncSetAttribute(k_gemm_node,
                         cudaFuncAttributeMaxDynamicSharedMemorySize,
                         (int)gsmem);
    cudaFuncSetAttribute(k_edge_fused,
                         cudaFuncAttributeMaxDynamicSharedMemorySize,
                         (int)esmem);

    // CSR build + weight prep + stat zeroing
    k_zero_cnt<<<(N + 255) / 256, 256>>>(N);
    k_hist<<<(E + 255) / 256, 256>>>(ei, E);
    k_scan<<<1, 1024>>>(N);
    k_fill<<<(E + 255) / 256, 256>>>(ei, E);
    k_prep<<<(NLAYERS * HID * HID + 255) / 256, 256>>>(Wrel, Wroot, W1, W2);

    k_input<<<N, HID>>>(x, Win, N);

    dim3 gN(HID / BN, (N + BM - 1) / BM);

    for (int l = 0; l < NLAYERS; l++) {
        k_aggr<<<(N + 7) / 8, 256>>>(N);
        k_gemm_node<<<gN, 256, gsmem>>>(l, brel + (size_t)l * HID, N);
        k_bn_apply<<<(N + 15) / 16, 256>>>(gamma + (size_t)l * HID,
                                           beta + (size_t)l * HID,
                                           1.0f / (float)N, N, l);
    }

    k_edge_fused<<<(E + ETM - 1) / ETM, 512, esmem>>>(ei, E, b1, b2, W3, b3,
                                                      out);
}